// round 13
// baseline (speedup 1.0000x reference)
#include <cuda_runtime.h>
#include <cuda_bf16.h>
#include <math.h>
#include <stdint.h>

// ---------------- problem constants ----------------------------------------
#define BSZ 2
#define TT 2048
#define DM 1024
#define DI 2048
#define NH 8
#define DS 64
#define DH 256
#define NROWS (BSZ*TT)          // 4096
#define EPSV 1e-6f
#define NCATP 1152              // B(512) | C(512) | dt(8) | pad -> 9*128
#define CHK 64
#define NCHKS (TT/CHK)          // 32

// ---------------- scratch (device globals) ---------------------------------
__device__ __nv_bfloat16 g_xn[(size_t)NROWS * DM];
__device__ __nv_bfloat16 g_xz[(size_t)NROWS * 2 * DI];
__device__ __nv_bfloat16 g_xs[(size_t)NROWS * DI];
__device__ __nv_bfloat16 g_bcdt[(size_t)NROWS * NCATP];
__device__ __nv_bfloat16 g_y [(size_t)NROWS * DI];
__device__ __nv_bfloat16 g_yi[(size_t)NROWS * DI];
__device__ float         g_hc [(size_t)16 * NCHKS * DS * DH];
__device__ __nv_bfloat16 g_hin[(size_t)16 * NCHKS * DS * DH];
__device__ float         g_S  [(size_t)16 * TT];
__device__ __nv_bfloat16 g_inw [(size_t)(2*DI) * DM];
__device__ __nv_bfloat16 g_wcat[(size_t)NCATP * DI];
__device__ __nv_bfloat16 g_outw[(size_t)DM * DI];

// ---------------- PTX helpers ----------------------------------------------
__device__ __forceinline__ uint32_t smem_u32(const void* p) {
    uint32_t a;
    asm("{ .reg .u64 t; cvta.to.shared.u64 t, %1; cvt.u32.u64 %0, t; }" : "=r"(a) : "l"(p));
    return a;
}

#define CP_ASYNC16(dst, src) \
    asm volatile("cp.async.cg.shared.global [%0], [%1], 16;" :: "r"(dst), "l"(src) : "memory")
#define CP_ASYNC4(dst, src) \
    asm volatile("cp.async.ca.shared.global [%0], [%1], 4;" :: "r"(dst), "l"(src) : "memory")
#define CP_COMMIT() asm volatile("cp.async.commit_group;" ::: "memory")
#define CP_WAIT1()  asm volatile("cp.async.wait_group 1;" ::: "memory")
#define CP_WAIT0()  asm volatile("cp.async.wait_group 0;" ::: "memory")

#define LDM_X4(r0, r1, r2, r3, addr) \
    asm volatile("ldmatrix.sync.aligned.m8n8.x4.shared.b16 {%0,%1,%2,%3}, [%4];" \
                 : "=r"(r0), "=r"(r1), "=r"(r2), "=r"(r3) : "r"(addr))
#define LDM_X4T(r0, r1, r2, r3, addr) \
    asm volatile("ldmatrix.sync.aligned.m8n8.x4.trans.shared.b16 {%0,%1,%2,%3}, [%4];" \
                 : "=r"(r0), "=r"(r1), "=r"(r2), "=r"(r3) : "r"(addr))

#define MMA16816(d, a0, a1, a2, a3, b0, b1) \
    asm volatile("mma.sync.aligned.m16n8k16.row.col.f32.bf16.bf16.f32 " \
                 "{%0,%1,%2,%3}, {%4,%5,%6,%7}, {%8,%9}, {%0,%1,%2,%3};" \
                 : "+f"((d)[0]), "+f"((d)[1]), "+f"((d)[2]), "+f"((d)[3]) \
                 : "r"(a0), "r"(a1), "r"(a2), "r"(a3), "r"(b0), "r"(b1))

// ---------------- bf16 mma.sync GEMM: C[M,N] = A[M,K] @ W[N,K]^T (+Res) ----
#define BM 128
#define BN 128
#define BK64 64
#define ROWB 144
#define SA_BYTES (BM * ROWB)
#define STG_BYTES (2 * SA_BYTES)
#define NST 3
#define GEMM_SMEM (NST * STG_BYTES)      // 110592

template <bool ADD_RES, bool OUT_BF16>
__global__ void __launch_bounds__(256)
gemm_mma(const __nv_bfloat16* __restrict__ A, const __nv_bfloat16* __restrict__ W,
         void* __restrict__ Cout, const float* __restrict__ Res,
         int M, int N, int K)
{
    extern __shared__ char sm[];
    uint32_t base = smem_u32(sm);

    int tid = threadIdx.x;
    int wid = tid >> 5, lane = tid & 31;
    int wm = wid >> 2, wn = wid & 3;
    int m0 = blockIdx.y * BM;
    int n0 = blockIdx.x * BN;

    const __nv_bfloat16* Ag = A + (size_t)m0 * K;
    const __nv_bfloat16* Wg = W + (size_t)n0 * K;

    float acc[4][4][4];
    #pragma unroll
    for (int i = 0; i < 4; i++)
        #pragma unroll
        for (int j = 0; j < 4; j++)
            #pragma unroll
            for (int f = 0; f < 4; f++) acc[i][j][f] = 0.f;

    int nk = K / BK64;

    auto load_stage = [&](int s, int k0) {
        uint32_t sA = base + s * STG_BYTES;
        uint32_t sB = sA + SA_BYTES;
        #pragma unroll
        for (int it = 0; it < 4; it++) {
            int i = tid + it * 256;
            int r = i >> 3, c = i & 7;
            CP_ASYNC16(sA + r * ROWB + c * 16, Ag + (size_t)r * K + k0 + c * 8);
        }
        #pragma unroll
        for (int it = 0; it < 4; it++) {
            int i = tid + it * 256;
            int r = i >> 3, c = i & 7;
            CP_ASYNC16(sB + r * ROWB + c * 16, Wg + (size_t)r * K + k0 + c * 8);
        }
    };

    load_stage(0, 0);      CP_COMMIT();
    load_stage(1, BK64);   CP_COMMIT();

    int stg = 0;
    for (int kt = 0; kt < nk; kt++) {
        CP_WAIT1();
        __syncthreads();

        int s2 = stg + 2; if (s2 >= NST) s2 -= NST;
        if (kt + 2 < nk) load_stage(s2, (kt + 2) * BK64);
        CP_COMMIT();

        uint32_t sA = base + stg * STG_BYTES;
        uint32_t sB = sA + SA_BYTES;

        #pragma unroll
        for (int ks = 0; ks < 4; ks++) {
            int colk = ks * 32 + (lane >> 4) * 16;           // bytes
            uint32_t a[4][4], b[2][4];
            #pragma unroll
            for (int i = 0; i < 4; i++) {
                int row = wm * 64 + i * 16 + (lane & 15);
                LDM_X4(a[i][0], a[i][1], a[i][2], a[i][3],
                       sA + (uint32_t)(row * ROWB + colk));
            }
            #pragma unroll
            for (int g = 0; g < 2; g++) {
                int row = wn * 32 + g * 16 + (lane & 15);
                LDM_X4(b[g][0], b[g][1], b[g][2], b[g][3],
                       sB + (uint32_t)(row * ROWB + colk));
            }
            #pragma unroll
            for (int i = 0; i < 4; i++) {
                MMA16816(acc[i][0], a[i][0], a[i][1], a[i][2], a[i][3], b[0][0], b[0][2]);
                MMA16816(acc[i][1], a[i][0], a[i][1], a[i][2], a[i][3], b[0][1], b[0][3]);
                MMA16816(acc[i][2], a[i][0], a[i][1], a[i][2], a[i][3], b[1][0], b[1][2]);
                MMA16816(acc[i][3], a[i][0], a[i][1], a[i][2], a[i][3], b[1][1], b[1][3]);
            }
        }
        stg++; if (stg >= NST) stg -= NST;
    }

    int gid = lane >> 2, t4 = lane & 3;
    #pragma unroll
    for (int i = 0; i < 4; i++) {
        int row0 = m0 + wm * 64 + i * 16 + gid;
        #pragma unroll
        for (int j = 0; j < 4; j++) {
            int col = n0 + wn * 32 + j * 8 + t4 * 2;
            size_t i0 = (size_t)row0 * N + col;
            size_t i1 = (size_t)(row0 + 8) * N + col;
            float2 v0 = make_float2(acc[i][j][0], acc[i][j][1]);
            float2 v1 = make_float2(acc[i][j][2], acc[i][j][3]);
            if (ADD_RES) {
                float2 r0 = *(const float2*)(Res + i0);
                float2 r1 = *(const float2*)(Res + i1);
                v0.x += r0.x; v0.y += r0.y;
                v1.x += r1.x; v1.y += r1.y;
            }
            if (OUT_BF16) {
                __nv_bfloat16* Cb = (__nv_bfloat16*)Cout;
                __nv_bfloat162 o0, o1;
                o0.x = __float2bfloat16(v0.x); o0.y = __float2bfloat16(v0.y);
                o1.x = __float2bfloat16(v1.x); o1.y = __float2bfloat16(v1.y);
                *(__nv_bfloat162*)(Cb + i0) = o0;
                *(__nv_bfloat162*)(Cb + i1) = o1;
            } else {
                float* Cf = (float*)Cout;
                *(float2*)(Cf + i0) = v0;
                *(float2*)(Cf + i1) = v1;
            }
        }
    }
}

// ---------------- weight conversion (vectorized) ----------------------------
__global__ void cvt_bf16_k(const float4* __restrict__ in, __nv_bfloat162* __restrict__ out, int n4)
{
    for (int i = blockIdx.x * 256 + threadIdx.x; i < n4; i += gridDim.x * 256) {
        float4 v = in[i];
        __nv_bfloat162 o0, o1;
        o0.x = __float2bfloat16(v.x); o0.y = __float2bfloat16(v.y);
        o1.x = __float2bfloat16(v.z); o1.y = __float2bfloat16(v.w);
        out[2 * i] = o0; out[2 * i + 1] = o1;
    }
}

// merged: out_w convert + wcat build
__global__ void prep2_k(const float* __restrict__ out_w, const float* __restrict__ Bw,
                        const float* __restrict__ Cw, const float* __restrict__ dtw)
{
    const int N2 = DM * DI / 4;          // 524288
    const int N3 = NCATP * DI / 4;       // 589824
    for (int idx = blockIdx.x * 256 + threadIdx.x; idx < N2 + N3; idx += gridDim.x * 256) {
        float4 v;
        __nv_bfloat162* dst;
        if (idx < N2) {
            v = ((const float4*)out_w)[idx];
            dst = (__nv_bfloat162*)g_outw + 2 * idx;
        } else {
            int i = idx - N2;
            int r = i >> 9;
            int kk = (i & 511) * 4;
            if (r < 512)       v = *(const float4*)(Bw + (size_t)r * DI + kk);
            else if (r < 1024) v = *(const float4*)(Cw + (size_t)(r - 512) * DI + kk);
            else if (r < 1032) v = *(const float4*)(dtw + (size_t)(r - 1024) * DI + kk);
            else               v = make_float4(0.f, 0.f, 0.f, 0.f);
            dst = (__nv_bfloat162*)g_wcat + 2 * i;
        }
        __nv_bfloat162 o0, o1;
        o0.x = __float2bfloat16(v.x); o0.y = __float2bfloat16(v.y);
        o1.x = __float2bfloat16(v.z); o1.y = __float2bfloat16(v.w);
        dst[0] = o0; dst[1] = o1;
    }
}

// ---------------- RMSNorm (float4, writes bf16) -----------------------------
__global__ void rmsnorm_k(const float* __restrict__ x, const float* __restrict__ w)
{
    int row = blockIdx.x;
    int tid = threadIdx.x;
    const float4* xr = (const float4*)(x + (size_t)row * DM);
    float4 v = xr[tid];
    float s = v.x * v.x + v.y * v.y + v.z * v.z + v.w * v.w;
    __shared__ float red[8];
    #pragma unroll
    for (int o = 16; o; o >>= 1) s += __shfl_xor_sync(0xffffffffu, s, o);
    if ((tid & 31) == 0) red[tid >> 5] = s;
    __syncthreads();
    if (tid < 8) {
        float t = red[tid];
        #pragma unroll
        for (int o = 4; o; o >>= 1) t += __shfl_xor_sync(0xffu, t, o);
        if (tid == 0) red[0] = rsqrtf(t / (float)DM + EPSV);
    }
    __syncthreads();
    float sc = red[0];
    float4 wv = ((const float4*)w)[tid];
    __nv_bfloat162 o0, o1;
    o0.x = __float2bfloat16(v.x * sc * wv.x);
    o0.y = __float2bfloat16(v.y * sc * wv.y);
    o1.x = __float2bfloat16(v.z * sc * wv.z);
    o1.y = __float2bfloat16(v.w * sc * wv.w);
    __nv_bfloat162* orow = (__nv_bfloat162*)(g_xn + (size_t)row * DM);
    orow[tid * 2] = o0;
    orow[tid * 2 + 1] = o1;
}

// ---------------- causal depthwise conv (K=4) + bias + SiLU -> bf16 ---------
__global__ void conv_silu_k(const float* __restrict__ cw, const float* __restrict__ cb)
{
    int c = blockIdx.x * 256 + threadIdx.x;
    int t0 = blockIdx.y * 4;
    int b = blockIdx.z;
    float4 w = ((const float4*)cw)[c];
    float bias = cb[c];
    size_t colbase = (size_t)b * TT * (2 * DI) + c;
    const size_t stride = 2 * DI;

    float xv[7];
    #pragma unroll
    for (int k = 0; k < 7; k++) {
        int t = t0 - 3 + k;
        xv[k] = (t >= 0) ? __bfloat162float(g_xz[colbase + (size_t)t * stride]) : 0.f;
    }
    size_t obase = ((size_t)b * TT + t0) * DI + c;
    #pragma unroll
    for (int i = 0; i < 4; i++) {
        float acc = bias + w.x * xv[i] + w.y * xv[i + 1] + w.z * xv[i + 2] + w.w * xv[i + 3];
        float sig = 1.f / (1.f + __expf(-acc));
        g_xs[obase + (size_t)i * DI] = __float2bfloat16(acc * sig);
    }
}

// ---------------- SSD phase A: intra-chunk + state contributions ------------
#define AO_C 0
#define AO_B 9216
#define AO_P 18432
#define AO_W 27648
#define AO_X 36864
#define AO_S 70656
#define AO_DT 70912
#define AO_WJ 71168
#define A_SMEM 71424

__global__ void __launch_bounds__(256)
chunk_intra_k(const float* __restrict__ A_log, const float* __restrict__ dtb)
{
    extern __shared__ char sm[];
    uint32_t base = smem_u32(sm);
    float* S  = (float*)(sm + AO_S);
    float* DT = (float*)(sm + AO_DT);
    float* WJ = (float*)(sm + AO_WJ);

    int tid = threadIdx.x;
    int wid = tid >> 5, lane = tid & 31;
    int wm = wid >> 2, wn = wid & 3;
    int chunk = blockIdx.x, h = blockIdx.y, b = blockIdx.z;
    int bh = b * NH + h;
    size_t rowbase = (size_t)b * TT + (size_t)chunk * CHK;

    const __nv_bfloat16* bsrc = g_bcdt + rowbase * NCATP + h * 64;
    for (int i = tid; i < 512; i += 256) {
        int r = i >> 3, c = i & 7;
        CP_ASYNC16(base + AO_B + r * 144 + c * 16, bsrc + (size_t)r * NCATP + c * 8);
        CP_ASYNC16(base + AO_C + r * 144 + c * 16, bsrc + (size_t)r * NCATP + 512 + c * 8);
    }
    for (int i = tid; i < 2048; i += 256) {
        int r = i >> 5, c = i & 31;
        CP_ASYNC16(base + AO_X + r * 528 + c * 16, g_xs + (rowbase + r) * DI + h * DH + c * 8);
    }
    CP_COMMIT();

    if (tid < 64) {
        float v = __bfloat162float(g_bcdt[(rowbase + tid) * NCATP + 1024 + h]) + dtb[h];
        DT[tid] = (v > 20.f) ? v : log1pf(expf(v));
    }
    CP_WAIT0();
    __syncthreads();

    float Ah = -__expf(A_log[h]);
    if (wid == 0) {
        float a0 = DT[lane] * Ah, a1 = DT[lane + 32] * Ah;
        #pragma unroll
        for (int off = 1; off < 32; off <<= 1) {
            float u0 = __shfl_up_sync(0xffffffffu, a0, off);
            float u1 = __shfl_up_sync(0xffffffffu, a1, off);
            if (lane >= off) { a0 += u0; a1 += u1; }
        }
        float tot = __shfl_sync(0xffffffffu, a0, 31);
        a1 += tot;
        S[lane] = a0; S[lane + 32] = a1;
    }
    __syncthreads();
    if (tid < 64) WJ[tid] = __expf(S[63] - S[tid]) * DT[tid];

    // GEMM1: G = C @ B^T
    float acc1[2][2][4];
    #pragma unroll
    for (int i = 0; i < 2; i++)
        #pragma unroll
        for (int j = 0; j < 2; j++)
            #pragma unroll
            for (int f = 0; f < 4; f++) acc1[i][j][f] = 0.f;

    #pragma unroll
    for (int ks = 0; ks < 4; ks++) {
        uint32_t a[2][4], bb[4];
        #pragma unroll
        for (int i = 0; i < 2; i++) {
            int row = wm * 32 + i * 16 + (lane & 15);
            LDM_X4(a[i][0], a[i][1], a[i][2], a[i][3],
                   base + AO_C + (uint32_t)(row * 144 + ks * 32 + (lane >> 4) * 16));
        }
        {
            int row = wn * 16 + (lane & 15);
            LDM_X4(bb[0], bb[1], bb[2], bb[3],
                   base + AO_B + (uint32_t)(row * 144 + ks * 32 + (lane >> 4) * 16));
        }
        #pragma unroll
        for (int i = 0; i < 2; i++) {
            MMA16816(acc1[i][0], a[i][0], a[i][1], a[i][2], a[i][3], bb[0], bb[2]);
            MMA16816(acc1[i][1], a[i][0], a[i][1], a[i][2], a[i][3], bb[1], bb[3]);
        }
    }

    int gid = lane >> 2, t4 = lane & 3;
    #pragma unroll
    for (int i = 0; i < 2; i++) {
        #pragma unroll
        for (int jd = 0; jd < 2; jd++) {
            int j0 = wn * 16 + jd * 8 + t4 * 2;
            #pragma unroll
            for (int hf = 0; hf < 2; hf++) {
                int t = wm * 32 + i * 16 + gid + hf * 8;
                float v0 = acc1[i][jd][hf * 2 + 0];
                float v1 = acc1[i][jd][hf * 2 + 1];
                float p0 = (t >= j0)     ? v0 * __expf(S[t] - S[j0])     * DT[j0]     : 0.f;
                float p1 = (t >= j0 + 1) ? v1 * __expf(S[t] - S[j0 + 1]) * DT[j0 + 1] : 0.f;
                __nv_bfloat162 pr;
                pr.x = __float2bfloat16(p0); pr.y = __float2bfloat16(p1);
                *(__nv_bfloat162*)(sm + AO_P + t * 144 + j0 * 2) = pr;
            }
        }
    }
    if (tid < 64) g_S[(size_t)bh * TT + chunk * CHK + tid] = S[tid];
    __syncthreads();

    for (int idx = tid; idx < 4096; idx += 256) {
        int j = idx >> 6, n = idx & 63;
        float bv = __bfloat162float(*(const __nv_bfloat16*)(sm + AO_B + j * 144 + n * 2));
        *(__nv_bfloat16*)(sm + AO_W + n * 144 + j * 2) = __float2bfloat16(bv * WJ[j]);
    }
    __syncthreads();

    // GEMM2: Y_intra = P @ X -> g_yi (bf16)
    {
        float acc[2][8][4];
        #pragma unroll
        for (int i = 0; i < 2; i++)
            #pragma unroll
            for (int j = 0; j < 8; j++)
                #pragma unroll
                for (int f = 0; f < 4; f++) acc[i][j][f] = 0.f;

        #pragma unroll
        for (int ks = 0; ks < 4; ks++) {
            uint32_t a[2][4];
            #pragma unroll
            for (int i = 0; i < 2; i++) {
                int row = wm * 32 + i * 16 + (lane & 15);
                LDM_X4(a[i][0], a[i][1], a[i][2], a[i][3],
                       base + AO_P + (uint32_t)(row * 144 + ks * 32 + (lane >> 4) * 16));
            }
            #pragma unroll
            for (int jj = 0; jj < 4; jj++) {
                int n0 = wn * 64 + jj * 16;
                int grp = lane >> 3, l8 = lane & 7;
                uint32_t addr = base + AO_X
                    + (uint32_t)(ks * 16 + (grp & 1) * 8 + l8) * 528
                    + (uint32_t)(n0 + (grp >> 1) * 8) * 2;
                uint32_t b0, b1, b2, b3;
                LDM_X4T(b0, b1, b2, b3, addr);
                #pragma unroll
                for (int i = 0; i < 2; i++) {
                    MMA16816(acc[i][jj * 2],     a[i][0], a[i][1], a[i][2], a[i][3], b0, b1);
                    MMA16816(acc[i][jj * 2 + 1], a[i][0], a[i][1], a[i][2], a[i][3], b2, b3);
                }
            }
        }
        #pragma unroll
        for (int i = 0; i < 2; i++)
            #pragma unroll
            for (int j8 = 0; j8 < 8; j8++)
                #pragma unroll
                for (int hf = 0; hf < 2; hf++) {
                    int t = wm * 32 + i * 16 + gid + hf * 8;
                    int d = wn * 64 + j8 * 8 + t4 * 2;
                    __nv_bfloat162 v;
                    v.x = __float2bfloat16(acc[i][j8][hf * 2]);
                    v.y = __float2bfloat16(acc[i][j8][hf * 2 + 1]);
                    *(__nv_bfloat162*)(g_yi + (rowbase + t) * DI + h * DH + d) = v;
                }
    }

    // GEMM3: H_c = Wt @ X -> g_hc fp32
    {
        float acc[2][8][4];
        #pragma unroll
        for (int i = 0; i < 2; i++)
            #pragma unroll
            for (int j = 0; j < 8; j++)
                #pragma unroll
                for (int f = 0; f < 4; f++) acc[i][j][f] = 0.f;

        #pragma unroll
        for (int ks = 0; ks < 4; ks++) {
            uint32_t a[2][4];
            #pragma unroll
            for (int i = 0; i < 2; i++) {
                int row = wm * 32 + i * 16 + (lane & 15);
                LDM_X4(a[i][0], a[i][1], a[i][2], a[i][3],
                       base + AO_W + (uint32_t)(row * 144 + ks * 32 + (lane >> 4) * 16));
            }
            #pragma unroll
            for (int jj = 0; jj < 4; jj++) {
                int n0 = wn * 64 + jj * 16;
                int grp = lane >> 3, l8 = lane & 7;
                uint32_t addr = base + AO_X
                    + (uint32_t)(ks * 16 + (grp & 1) * 8 + l8) * 528
                    + (uint32_t)(n0 + (grp >> 1) * 8) * 2;
                uint32_t b0, b1, b2, b3;
                LDM_X4T(b0, b1, b2, b3, addr);
                #pragma unroll
                for (int i = 0; i < 2; i++) {
                    MMA16816(acc[i][jj * 2],     a[i][0], a[i][1], a[i][2], a[i][3], b0, b1);
                    MMA16816(acc[i][jj * 2 + 1], a[i][0], a[i][1], a[i][2], a[i][3], b2, b3);
                }
            }
        }
        #pragma unroll
        for (int i = 0; i < 2; i++)
            #pragma unroll
            for (int j8 = 0; j8 < 8; j8++)
                #pragma unroll
                for (int hf = 0; hf < 2; hf++) {
                    int n = wm * 32 + i * 16 + gid + hf * 8;
                    int d = wn * 64 + j8 * 8 + t4 * 2;
                    float2 v = make_float2(acc[i][j8][hf * 2], acc[i][j8][hf * 2 + 1]);
                    *(float2*)(g_hc + (((size_t)bh * NCHKS + chunk) * DS + n) * DH + d) = v;
                }
    }
}

// ---------------- SSD phase B: cross-chunk state recurrence (prefetched) ----
// grid (16 d-slices, 8 h, 2 b) = 256 CTAs; thread owns (n, 4 d) states.
__global__ void __launch_bounds__(256)
state_scan_k()
{
    int dsl = blockIdx.x, h = blockIdx.y, b = blockIdx.z;
    int bh = b * NH + h;
    int tid = threadIdx.x;
    int n = tid >> 2;
    int dbase = dsl * 16 + (tid & 3) * 4;

    float4 hst = make_float4(0.f, 0.f, 0.f, 0.f);
    const size_t cstride = (size_t)DS * DH;
    size_t hb0 = ((size_t)bh * NCHKS * DS + n) * DH + dbase;

    float4 v = *(const float4*)(g_hc + hb0);    // prefetch chunk 0
    for (int c = 0; c < NCHKS; c++) {
        float decay = __expf(g_S[(size_t)bh * TT + c * CHK + CHK - 1]);
        size_t hb = hb0 + (size_t)c * cstride;
        __nv_bfloat162 p0, p1;
        p0.x = __float2bfloat16(hst.x); p0.y = __float2bfloat16(hst.y);
        p1.x = __float2bfloat16(hst.z); p1.y = __float2bfloat16(hst.w);
        *(__nv_bfloat162*)(g_hin + hb) = p0;
        *(__nv_bfloat162*)(g_hin + hb + 2) = p1;

        float4 vn = make_float4(0.f, 0.f, 0.f, 0.f);
        if (c + 1 < NCHKS) vn = *(const float4*)(g_hc + hb + cstride);  // prefetch
        hst.x = decay * hst.x + v.x;
        hst.y = decay * hst.y + v.y;
        hst.z = decay * hst.z + v.z;
        hst.w = decay * hst.w + v.w;
        v = vn;
    }
}

// ---------------- SSD phase C: inter-chunk Y + combine + gate ---------------
#define CO_C 0
#define CO_H 9216
#define CO_S 43008
#define C_SMEM 43264

__global__ void __launch_bounds__(256)
chunk_inter_k(const float* __restrict__ Dp)
{
    extern __shared__ char sm[];
    uint32_t base = smem_u32(sm);
    float* S = (float*)(sm + CO_S);

    int tid = threadIdx.x;
    int wid = tid >> 5, lane = tid & 31;
    int wm = wid >> 2, wn = wid & 3;
    int chunk = blockIdx.x, h = blockIdx.y, b = blockIdx.z;
    int bh = b * NH + h;
    size_t rowbase = (size_t)b * TT + (size_t)chunk * CHK;

    const __nv_bfloat16* csrc = g_bcdt + rowbase * NCATP + 512 + h * 64;
    for (int i = tid; i < 512; i += 256) {
        int r = i >> 3, c = i & 7;
        CP_ASYNC16(base + CO_C + r * 144 + c * 16, csrc + (size_t)r * NCATP + c * 8);
    }
    const __nv_bfloat16* hsrc = g_hin + ((size_t)bh * NCHKS + chunk) * DS * DH;
    for (int i = tid; i < 2048; i += 256) {
        int r = i >> 5, c = i & 31;
        CP_ASYNC16(base + CO_H + r * 528 + c * 16, hsrc + (size_t)r * DH + c * 8);
    }
    if (tid < 64)
        CP_ASYNC4(base + CO_S + tid * 4, g_S + (size_t)bh * TT + chunk * CHK + tid);
    CP_COMMIT();
    CP_WAIT0();
    __syncthreads();

    float acc[2][8][4];
    #pragma unroll
    for (int i = 0; i < 2; i++)
        #pragma unroll
        for (int j = 0; j < 8; j++)
            #pragma unroll
            for (int f = 0; f < 4; f++) acc[i][j][f] = 0.f;

    #pragma unroll
    for (int ks = 0; ks < 4; ks++) {
        uint32_t a[2][4];
        #pragma unroll
        for (int i = 0; i < 2; i++) {
            int row = wm * 32 + i * 16 + (lane & 15);
            LDM_X4(a[i][0], a[i][1], a[i][2], a[i][3],
                   base + CO_C + (uint32_t)(row * 144 + ks * 32 + (lane >> 4) * 16));
        }
        #pragma unroll
        for (int jj = 0; jj < 4; jj++) {
            int n0 = wn * 64 + jj * 16;
            int grp = lane >> 3, l8 = lane & 7;
            uint32_t addr = base + CO_H
                + (uint32_t)(ks * 16 + (grp & 1) * 8 + l8) * 528
                + (uint32_t)(n0 + (grp >> 1) * 8) * 2;
            uint32_t b0, b1, b2, b3;
            LDM_X4T(b0, b1, b2, b3, addr);
            #pragma unroll
            for (int i = 0; i < 2; i++) {
                MMA16816(acc[i][jj * 2],     a[i][0], a[i][1], a[i][2], a[i][3], b0, b1);
                MMA16816(acc[i][jj * 2 + 1], a[i][0], a[i][1], a[i][2], a[i][3], b2, b3);
            }
        }
    }

    float Dh = Dp[h];
    int gid = lane >> 2, t4 = lane & 3;
    #pragma unroll
    for (int i = 0; i < 2; i++)
        #pragma unroll
        for (int j8 = 0; j8 < 8; j8++)
            #pragma unroll
            for (int hf = 0; hf < 2; hf++) {
                int t = wm * 32 + i * 16 + gid + hf * 8;
                int d = wn * 64 + j8 * 8 + t4 * 2;
                float et = __expf(S[t]);
                size_t gi = (rowbase + t) * DI + h * DH + d;
                __nv_bfloat162 yi = *(const __nv_bfloat162*)(g_yi + gi);
                __nv_bfloat162 xv = *(const __nv_bfloat162*)(g_xs + gi);
                __nv_bfloat162 z2 = *(const __nv_bfloat162*)(g_xz + (rowbase + t) * (2 * DI) + DI + h * DH + d);
                float z0 = __bfloat162float(z2.x), z1 = __bfloat162float(z2.y);
                float y0 = acc[i][j8][hf * 2 + 0] * et + __bfloat162float(yi.x) + Dh * __bfloat162float(xv.x);
                float y1 = acc[i][j8][hf * 2 + 1] * et + __bfloat162float(yi.y) + Dh * __bfloat162float(xv.y);
                float s0 = z0 / (1.f + __expf(-z0));
                float s1 = z1 / (1.f + __expf(-z1));
                __nv_bfloat162 o;
                o.x = __float2bfloat16(y0 * s0);
                o.y = __float2bfloat16(y1 * s1);
                *(__nv_bfloat162*)(g_y + gi) = o;
            }
}

// ---------------- launch ----------------------------------------------------
extern "C" void kernel_launch(void* const* d_in, const int* in_sizes, int n_in,
                              void* d_out, int out_size)
{
    const float* x      = (const float*)d_in[0];
    const float* norm_w = (const float*)d_in[1];
    const float* in_w   = (const float*)d_in[2];
    const float* conv_w = (const float*)d_in[3];
    const float* conv_b = (const float*)d_in[4];
    const float* A_log  = (const float*)d_in[5];
    const float* B_w    = (const float*)d_in[6];
    const float* C_w    = (const float*)d_in[7];
    const float* dt_w   = (const float*)d_in[8];
    const float* dt_b   = (const float*)d_in[9];
    const float* Dp     = (const float*)d_in[10];
    const float* out_w  = (const float*)d_in[11];
    float* out = (float*)d_out;

    __nv_bfloat16 *p_xn, *p_xs, *p_y, *p_inw, *p_wcat, *p_outw, *p_bcdt, *p_xz;
    cudaGetSymbolAddress((void**)&p_xn, g_xn);
    cudaGetSymbolAddress((void**)&p_xz, g_xz);
    cudaGetSymbolAddress((void**)&p_xs, g_xs);
    cudaGetSymbolAddress((void**)&p_bcdt, g_bcdt);
    cudaGetSymbolAddress((void**)&p_y, g_y);
    cudaGetSymbolAddress((void**)&p_inw, g_inw);
    cudaGetSymbolAddress((void**)&p_wcat, g_wcat);
    cudaGetSymbolAddress((void**)&p_outw, g_outw);

    cudaFuncSetAttribute(gemm_mma<false, true>,  cudaFuncAttributeMaxDynamicSharedMemorySize, GEMM_SMEM);
    cudaFuncSetAttribute(gemm_mma<true, false>,  cudaFuncAttributeMaxDynamicSharedMemorySize, GEMM_SMEM);
    cudaFuncSetAttribute(chunk_intra_k, cudaFuncAttributeMaxDynamicSharedMemorySize, A_SMEM);
    cudaFuncSetAttribute(chunk_inter_k, cudaFuncAttributeMaxDynamicSharedMemorySize, C_SMEM);

    // [0] in_w -> bf16
    cvt_bf16_k<<<256, 256>>>((const float4*)in_w, (__nv_bfloat162*)p_inw, 2 * DI * DM / 4);
    // [1] RMSNorm -> bf16
    rmsnorm_k<<<NROWS, 256>>>(x, norm_w);
    // [2] out_w -> bf16 + fused [B|C|dt] weight (merged)
    prep2_k<<<256, 256>>>(out_w, B_w, C_w, dt_w);
    // [3] xz = xn @ in_w^T -> bf16  (ncu capture slot)
    gemm_mma<false, true><<<dim3(4096 / BN, NROWS / BM), 256, GEMM_SMEM>>>(
        p_xn, p_inw, (void*)p_xz, nullptr, NROWS, 2 * DI, DM);
    // [4] causal conv + SiLU -> bf16
    conv_silu_k<<<dim3(DI / 256, TT / 4, BSZ), 256>>>(conv_w, conv_b);
    // [5] [B | C | dt] = xs @ wcat^T -> bf16
    gemm_mma<false, true><<<dim3(NCATP / BN, NROWS / BM), 256, GEMM_SMEM>>>(
        p_xs, p_wcat, (void*)p_bcdt, nullptr, NROWS, NCATP, DI);
    // [6] SSD phase A
    chunk_intra_k<<<dim3(NCHKS, NH, BSZ), 256, A_SMEM>>>(A_log, dt_b);
    // [7] SSD phase B (prefetched, 256 CTAs)
    state_scan_k<<<dim3(16, NH, BSZ), 256>>>();
    // [8] SSD phase C
    chunk_inter_k<<<dim3(NCHKS, NH, BSZ), 256, C_SMEM>>>(Dp);
    // [9] out = y @ out_w^T + residual
    gemm_mma<true, false><<<dim3(1024 / BN, NROWS / BM), 256, GEMM_SMEM>>>(
        p_y, p_outw, (void*)out, x, NROWS, DM, DI);
}

// round 14
// speedup vs baseline: 1.0983x; 1.0983x over previous
#include <cuda_runtime.h>
#include <cuda_bf16.h>
#include <math.h>
#include <stdint.h>

// ---------------- problem constants ----------------------------------------
#define BSZ 2
#define TT 2048
#define DM 1024
#define DI 2048
#define NH 8
#define DS 64
#define DH 256
#define NROWS (BSZ*TT)          // 4096
#define EPSV 1e-6f
#define NCATP 1152              // B(512) | C(512) | dt(8) | pad -> 9*128
#define CHK 64
#define NCHKS (TT/CHK)          // 32

// ---------------- scratch (device globals) ---------------------------------
__device__ __nv_bfloat16 g_xn[(size_t)NROWS * DM];
__device__ __nv_bfloat16 g_xz[(size_t)NROWS * 2 * DI];
__device__ __nv_bfloat16 g_xs[(size_t)NROWS * DI];
__device__ __nv_bfloat16 g_bcdt[(size_t)NROWS * NCATP];
__device__ __nv_bfloat16 g_y [(size_t)NROWS * DI];
__device__ __nv_bfloat16 g_yi[(size_t)NROWS * DI];
__device__ float         g_hc [(size_t)16 * NCHKS * DS * DH];
__device__ __nv_bfloat16 g_hin[(size_t)16 * NCHKS * DS * DH];
__device__ float         g_S  [(size_t)16 * TT];
__device__ __nv_bfloat16 g_inw [(size_t)(2*DI) * DM];
__device__ __nv_bfloat16 g_wcat[(size_t)NCATP * DI];
__device__ __nv_bfloat16 g_outw[(size_t)DM * DI];

// ---------------- PTX helpers ----------------------------------------------
__device__ __forceinline__ uint32_t smem_u32(const void* p) {
    uint32_t a;
    asm("{ .reg .u64 t; cvta.to.shared.u64 t, %1; cvt.u32.u64 %0, t; }" : "=r"(a) : "l"(p));
    return a;
}

#define CP_ASYNC16(dst, src) \
    asm volatile("cp.async.cg.shared.global [%0], [%1], 16;" :: "r"(dst), "l"(src) : "memory")
#define CP_ASYNC4(dst, src) \
    asm volatile("cp.async.ca.shared.global [%0], [%1], 4;" :: "r"(dst), "l"(src) : "memory")
#define CP_COMMIT() asm volatile("cp.async.commit_group;" ::: "memory")
#define CP_WAIT1()  asm volatile("cp.async.wait_group 1;" ::: "memory")
#define CP_WAIT0()  asm volatile("cp.async.wait_group 0;" ::: "memory")

#define LDM_X4(r0, r1, r2, r3, addr) \
    asm volatile("ldmatrix.sync.aligned.m8n8.x4.shared.b16 {%0,%1,%2,%3}, [%4];" \
                 : "=r"(r0), "=r"(r1), "=r"(r2), "=r"(r3) : "r"(addr))
#define LDM_X4T(r0, r1, r2, r3, addr) \
    asm volatile("ldmatrix.sync.aligned.m8n8.x4.trans.shared.b16 {%0,%1,%2,%3}, [%4];" \
                 : "=r"(r0), "=r"(r1), "=r"(r2), "=r"(r3) : "r"(addr))
#define LDM_X2(r0, r1, addr) \
    asm volatile("ldmatrix.sync.aligned.m8n8.x2.shared.b16 {%0,%1}, [%2];" \
                 : "=r"(r0), "=r"(r1) : "r"(addr))

#define MMA16816(d, a0, a1, a2, a3, b0, b1) \
    asm volatile("mma.sync.aligned.m16n8k16.row.col.f32.bf16.bf16.f32 " \
                 "{%0,%1,%2,%3}, {%4,%5,%6,%7}, {%8,%9}, {%0,%1,%2,%3};" \
                 : "+f"((d)[0]), "+f"((d)[1]), "+f"((d)[2]), "+f"((d)[3]) \
                 : "r"(a0), "r"(a1), "r"(a2), "r"(a3), "r"(b0), "r"(b1))

// ---------------- bf16 mma.sync GEMM: C[M,N] = A[M,K] @ W[N,K]^T (+Res) ----
#define BM 128
#define BN 128
#define BK64 64
#define ROWB 144
#define SA_BYTES (BM * ROWB)
#define STG_BYTES (2 * SA_BYTES)
#define NST 3
#define GEMM_SMEM (NST * STG_BYTES)      // 110592

template <bool ADD_RES, bool OUT_BF16>
__global__ void __launch_bounds__(256)
gemm_mma(const __nv_bfloat16* __restrict__ A, const __nv_bfloat16* __restrict__ W,
         void* __restrict__ Cout, const float* __restrict__ Res,
         int M, int N, int K)
{
    extern __shared__ char sm[];
    uint32_t base = smem_u32(sm);

    int tid = threadIdx.x;
    int wid = tid >> 5, lane = tid & 31;
    int wm = wid >> 2, wn = wid & 3;
    int m0 = blockIdx.y * BM;
    int n0 = blockIdx.x * BN;

    const __nv_bfloat16* Ag = A + (size_t)m0 * K;
    const __nv_bfloat16* Wg = W + (size_t)n0 * K;

    float acc[4][4][4];
    #pragma unroll
    for (int i = 0; i < 4; i++)
        #pragma unroll
        for (int j = 0; j < 4; j++)
            #pragma unroll
            for (int f = 0; f < 4; f++) acc[i][j][f] = 0.f;

    int nk = K / BK64;

    auto load_stage = [&](int s, int k0) {
        uint32_t sA = base + s * STG_BYTES;
        uint32_t sB = sA + SA_BYTES;
        #pragma unroll
        for (int it = 0; it < 4; it++) {
            int i = tid + it * 256;
            int r = i >> 3, c = i & 7;
            CP_ASYNC16(sA + r * ROWB + c * 16, Ag + (size_t)r * K + k0 + c * 8);
        }
        #pragma unroll
        for (int it = 0; it < 4; it++) {
            int i = tid + it * 256;
            int r = i >> 3, c = i & 7;
            CP_ASYNC16(sB + r * ROWB + c * 16, Wg + (size_t)r * K + k0 + c * 8);
        }
    };

    load_stage(0, 0);      CP_COMMIT();
    load_stage(1, BK64);   CP_COMMIT();

    int stg = 0;
    for (int kt = 0; kt < nk; kt++) {
        CP_WAIT1();
        __syncthreads();

        int s2 = stg + 2; if (s2 >= NST) s2 -= NST;
        if (kt + 2 < nk) load_stage(s2, (kt + 2) * BK64);
        CP_COMMIT();

        uint32_t sA = base + stg * STG_BYTES;
        uint32_t sB = sA + SA_BYTES;

        #pragma unroll
        for (int ks = 0; ks < 4; ks++) {
            int colA = ks * 32 + (lane >> 4) * 16;
            int colB = ks * 32 + ((lane >> 3) & 1) * 16;
            uint32_t a[4][4], b[4][2];
            #pragma unroll
            for (int i = 0; i < 4; i++) {
                int row = wm * 64 + i * 16 + (lane & 15);
                LDM_X4(a[i][0], a[i][1], a[i][2], a[i][3],
                       sA + (uint32_t)(row * ROWB + colA));
            }
            #pragma unroll
            for (int j = 0; j < 4; j++) {
                int row = wn * 32 + j * 8 + (lane & 7);
                LDM_X2(b[j][0], b[j][1],
                       sB + (uint32_t)(row * ROWB + colB));
            }
            #pragma unroll
            for (int i = 0; i < 4; i++)
                #pragma unroll
                for (int j = 0; j < 4; j++)
                    MMA16816(acc[i][j], a[i][0], a[i][1], a[i][2], a[i][3],
                             b[j][0], b[j][1]);
        }
        stg++; if (stg >= NST) stg -= NST;
    }

    int gid = lane >> 2, t4 = lane & 3;
    #pragma unroll
    for (int i = 0; i < 4; i++) {
        int row0 = m0 + wm * 64 + i * 16 + gid;
        #pragma unroll
        for (int j = 0; j < 4; j++) {
            int col = n0 + wn * 32 + j * 8 + t4 * 2;
            size_t i0 = (size_t)row0 * N + col;
            size_t i1 = (size_t)(row0 + 8) * N + col;
            float2 v0 = make_float2(acc[i][j][0], acc[i][j][1]);
            float2 v1 = make_float2(acc[i][j][2], acc[i][j][3]);
            if (ADD_RES) {
                float2 r0 = *(const float2*)(Res + i0);
                float2 r1 = *(const float2*)(Res + i1);
                v0.x += r0.x; v0.y += r0.y;
                v1.x += r1.x; v1.y += r1.y;
            }
            if (OUT_BF16) {
                __nv_bfloat16* Cb = (__nv_bfloat16*)Cout;
                __nv_bfloat162 o0, o1;
                o0.x = __float2bfloat16(v0.x); o0.y = __float2bfloat16(v0.y);
                o1.x = __float2bfloat16(v1.x); o1.y = __float2bfloat16(v1.y);
                *(__nv_bfloat162*)(Cb + i0) = o0;
                *(__nv_bfloat162*)(Cb + i1) = o1;
            } else {
                float* Cf = (float*)Cout;
                *(float2*)(Cf + i0) = v0;
                *(float2*)(Cf + i1) = v1;
            }
        }
    }
}

// ---------------- weight conversion (vectorized) ----------------------------
__global__ void cvt_bf16_k(const float4* __restrict__ in, __nv_bfloat162* __restrict__ out, int n4)
{
    for (int i = blockIdx.x * 256 + threadIdx.x; i < n4; i += gridDim.x * 256) {
        float4 v = in[i];
        __nv_bfloat162 o0, o1;
        o0.x = __float2bfloat16(v.x); o0.y = __float2bfloat16(v.y);
        o1.x = __float2bfloat16(v.z); o1.y = __float2bfloat16(v.w);
        out[2 * i] = o0; out[2 * i + 1] = o1;
    }
}

// merged: out_w convert + wcat build
__global__ void prep2_k(const float* __restrict__ out_w, const float* __restrict__ Bw,
                        const float* __restrict__ Cw, const float* __restrict__ dtw)
{
    const int N2 = DM * DI / 4;          // 524288
    const int N3 = NCATP * DI / 4;       // 589824
    for (int idx = blockIdx.x * 256 + threadIdx.x; idx < N2 + N3; idx += gridDim.x * 256) {
        float4 v;
        __nv_bfloat162* dst;
        if (idx < N2) {
            v = ((const float4*)out_w)[idx];
            dst = (__nv_bfloat162*)g_outw + 2 * idx;
        } else {
            int i = idx - N2;
            int r = i >> 9;
            int kk = (i & 511) * 4;
            if (r < 512)       v = *(const float4*)(Bw + (size_t)r * DI + kk);
            else if (r < 1024) v = *(const float4*)(Cw + (size_t)(r - 512) * DI + kk);
            else if (r < 1032) v = *(const float4*)(dtw + (size_t)(r - 1024) * DI + kk);
            else               v = make_float4(0.f, 0.f, 0.f, 0.f);
            dst = (__nv_bfloat162*)g_wcat + 2 * i;
        }
        __nv_bfloat162 o0, o1;
        o0.x = __float2bfloat16(v.x); o0.y = __float2bfloat16(v.y);
        o1.x = __float2bfloat16(v.z); o1.y = __float2bfloat16(v.w);
        dst[0] = o0; dst[1] = o1;
    }
}

// ---------------- RMSNorm (float4, writes bf16) -----------------------------
__global__ void rmsnorm_k(const float* __restrict__ x, const float* __restrict__ w)
{
    int row = blockIdx.x;
    int tid = threadIdx.x;
    const float4* xr = (const float4*)(x + (size_t)row * DM);
    float4 v = xr[tid];
    float s = v.x * v.x + v.y * v.y + v.z * v.z + v.w * v.w;
    __shared__ float red[8];
    #pragma unroll
    for (int o = 16; o; o >>= 1) s += __shfl_xor_sync(0xffffffffu, s, o);
    if ((tid & 31) == 0) red[tid >> 5] = s;
    __syncthreads();
    if (tid < 8) {
        float t = red[tid];
        #pragma unroll
        for (int o = 4; o; o >>= 1) t += __shfl_xor_sync(0xffu, t, o);
        if (tid == 0) red[0] = rsqrtf(t / (float)DM + EPSV);
    }
    __syncthreads();
    float sc = red[0];
    float4 wv = ((const float4*)w)[tid];
    __nv_bfloat162 o0, o1;
    o0.x = __float2bfloat16(v.x * sc * wv.x);
    o0.y = __float2bfloat16(v.y * sc * wv.y);
    o1.x = __float2bfloat16(v.z * sc * wv.z);
    o1.y = __float2bfloat16(v.w * sc * wv.w);
    __nv_bfloat162* orow = (__nv_bfloat162*)(g_xn + (size_t)row * DM);
    orow[tid * 2] = o0;
    orow[tid * 2 + 1] = o1;
}

// ---------------- causal depthwise conv (K=4) + bias + SiLU -> bf16 ---------
__global__ void conv_silu_k(const float* __restrict__ cw, const float* __restrict__ cb)
{
    int c = blockIdx.x * 256 + threadIdx.x;
    int t0 = blockIdx.y * 4;
    int b = blockIdx.z;
    float4 w = ((const float4*)cw)[c];
    float bias = cb[c];
    size_t colbase = (size_t)b * TT * (2 * DI) + c;
    const size_t stride = 2 * DI;

    float xv[7];
    #pragma unroll
    for (int k = 0; k < 7; k++) {
        int t = t0 - 3 + k;
        xv[k] = (t >= 0) ? __bfloat162float(g_xz[colbase + (size_t)t * stride]) : 0.f;
    }
    size_t obase = ((size_t)b * TT + t0) * DI + c;
    #pragma unroll
    for (int i = 0; i < 4; i++) {
        float acc = bias + w.x * xv[i] + w.y * xv[i + 1] + w.z * xv[i + 2] + w.w * xv[i + 3];
        float sig = 1.f / (1.f + __expf(-acc));
        g_xs[obase + (size_t)i * DI] = __float2bfloat16(acc * sig);
    }
}

// ---------------- SSD phase A: intra-chunk + state contributions ------------
#define AO_C 0
#define AO_B 9216
#define AO_P 18432
#define AO_W 27648
#define AO_X 36864
#define AO_S 70656
#define AO_DT 70912
#define AO_WJ 71168
#define A_SMEM 71424

__global__ void __launch_bounds__(256)
chunk_intra_k(const float* __restrict__ A_log, const float* __restrict__ dtb)
{
    extern __shared__ char sm[];
    uint32_t base = smem_u32(sm);
    float* S  = (float*)(sm + AO_S);
    float* DT = (float*)(sm + AO_DT);
    float* WJ = (float*)(sm + AO_WJ);

    int tid = threadIdx.x;
    int wid = tid >> 5, lane = tid & 31;
    int wm = wid >> 2, wn = wid & 3;
    int chunk = blockIdx.x, h = blockIdx.y, b = blockIdx.z;
    int bh = b * NH + h;
    size_t rowbase = (size_t)b * TT + (size_t)chunk * CHK;

    const __nv_bfloat16* bsrc = g_bcdt + rowbase * NCATP + h * 64;
    for (int i = tid; i < 512; i += 256) {
        int r = i >> 3, c = i & 7;
        CP_ASYNC16(base + AO_B + r * 144 + c * 16, bsrc + (size_t)r * NCATP + c * 8);
        CP_ASYNC16(base + AO_C + r * 144 + c * 16, bsrc + (size_t)r * NCATP + 512 + c * 8);
    }
    for (int i = tid; i < 2048; i += 256) {
        int r = i >> 5, c = i & 31;
        CP_ASYNC16(base + AO_X + r * 528 + c * 16, g_xs + (rowbase + r) * DI + h * DH + c * 8);
    }
    CP_COMMIT();

    if (tid < 64) {
        float v = __bfloat162float(g_bcdt[(rowbase + tid) * NCATP + 1024 + h]) + dtb[h];
        DT[tid] = (v > 20.f) ? v : log1pf(expf(v));
    }
    CP_WAIT0();
    __syncthreads();

    float Ah = -__expf(A_log[h]);
    if (wid == 0) {
        float a0 = DT[lane] * Ah, a1 = DT[lane + 32] * Ah;
        #pragma unroll
        for (int off = 1; off < 32; off <<= 1) {
            float u0 = __shfl_up_sync(0xffffffffu, a0, off);
            float u1 = __shfl_up_sync(0xffffffffu, a1, off);
            if (lane >= off) { a0 += u0; a1 += u1; }
        }
        float tot = __shfl_sync(0xffffffffu, a0, 31);
        a1 += tot;
        S[lane] = a0; S[lane + 32] = a1;
    }
    __syncthreads();
    if (tid < 64) WJ[tid] = __expf(S[63] - S[tid]) * DT[tid];

    // GEMM1: G = C @ B^T
    float acc1[2][2][4];
    #pragma unroll
    for (int i = 0; i < 2; i++)
        #pragma unroll
        for (int j = 0; j < 2; j++)
            #pragma unroll
            for (int f = 0; f < 4; f++) acc1[i][j][f] = 0.f;

    #pragma unroll
    for (int ks = 0; ks < 4; ks++) {
        uint32_t a[2][4], bb[4];
        #pragma unroll
        for (int i = 0; i < 2; i++) {
            int row = wm * 32 + i * 16 + (lane & 15);
            LDM_X4(a[i][0], a[i][1], a[i][2], a[i][3],
                   base + AO_C + (uint32_t)(row * 144 + ks * 32 + (lane >> 4) * 16));
        }
        {
            int row = wn * 16 + (lane & 15);
            LDM_X4(bb[0], bb[1], bb[2], bb[3],
                   base + AO_B + (uint32_t)(row * 144 + ks * 32 + (lane >> 4) * 16));
        }
        #pragma unroll
        for (int i = 0; i < 2; i++) {
            MMA16816(acc1[i][0], a[i][0], a[i][1], a[i][2], a[i][3], bb[0], bb[2]);
            MMA16816(acc1[i][1], a[i][0], a[i][1], a[i][2], a[i][3], bb[1], bb[3]);
        }
    }

    int gid = lane >> 2, t4 = lane & 3;
    #pragma unroll
    for (int i = 0; i < 2; i++) {
        #pragma unroll
        for (int jd = 0; jd < 2; jd++) {
            int j0 = wn * 16 + jd * 8 + t4 * 2;
            #pragma unroll
            for (int hf = 0; hf < 2; hf++) {
                int t = wm * 32 + i * 16 + gid + hf * 8;
                float v0 = acc1[i][jd][hf * 2 + 0];
                float v1 = acc1[i][jd][hf * 2 + 1];
                float p0 = (t >= j0)     ? v0 * __expf(S[t] - S[j0])     * DT[j0]     : 0.f;
                float p1 = (t >= j0 + 1) ? v1 * __expf(S[t] - S[j0 + 1]) * DT[j0 + 1] : 0.f;
                __nv_bfloat162 pr;
                pr.x = __float2bfloat16(p0); pr.y = __float2bfloat16(p1);
                *(__nv_bfloat162*)(sm + AO_P + t * 144 + j0 * 2) = pr;
            }
        }
    }
    if (tid < 64) g_S[(size_t)bh * TT + chunk * CHK + tid] = S[tid];
    __syncthreads();

    for (int idx = tid; idx < 4096; idx += 256) {
        int j = idx >> 6, n = idx & 63;
        float bv = __bfloat162float(*(const __nv_bfloat16*)(sm + AO_B + j * 144 + n * 2));
        *(__nv_bfloat16*)(sm + AO_W + n * 144 + j * 2) = __float2bfloat16(bv * WJ[j]);
    }
    __syncthreads();

    // GEMM2: Y_intra = P @ X -> g_yi (bf16)
    {
        float acc[2][8][4];
        #pragma unroll
        for (int i = 0; i < 2; i++)
            #pragma unroll
            for (int j = 0; j < 8; j++)
                #pragma unroll
                for (int f = 0; f < 4; f++) acc[i][j][f] = 0.f;

        #pragma unroll
        for (int ks = 0; ks < 4; ks++) {
            uint32_t a[2][4];
            #pragma unroll
            for (int i = 0; i < 2; i++) {
                int row = wm * 32 + i * 16 + (lane & 15);
                LDM_X4(a[i][0], a[i][1], a[i][2], a[i][3],
                       base + AO_P + (uint32_t)(row * 144 + ks * 32 + (lane >> 4) * 16));
            }
            #pragma unroll
            for (int jj = 0; jj < 4; jj++) {
                int n0 = wn * 64 + jj * 16;
                int grp = lane >> 3, l8 = lane & 7;
                uint32_t addr = base + AO_X
                    + (uint32_t)(ks * 16 + (grp & 1) * 8 + l8) * 528
                    + (uint32_t)(n0 + (grp >> 1) * 8) * 2;
                uint32_t b0, b1, b2, b3;
                LDM_X4T(b0, b1, b2, b3, addr);
                #pragma unroll
                for (int i = 0; i < 2; i++) {
                    MMA16816(acc[i][jj * 2],     a[i][0], a[i][1], a[i][2], a[i][3], b0, b1);
                    MMA16816(acc[i][jj * 2 + 1], a[i][0], a[i][1], a[i][2], a[i][3], b2, b3);
                }
            }
        }
        #pragma unroll
        for (int i = 0; i < 2; i++)
            #pragma unroll
            for (int j8 = 0; j8 < 8; j8++)
                #pragma unroll
                for (int hf = 0; hf < 2; hf++) {
                    int t = wm * 32 + i * 16 + gid + hf * 8;
                    int d = wn * 64 + j8 * 8 + t4 * 2;
                    __nv_bfloat162 v;
                    v.x = __float2bfloat16(acc[i][j8][hf * 2]);
                    v.y = __float2bfloat16(acc[i][j8][hf * 2 + 1]);
                    *(__nv_bfloat162*)(g_yi + (rowbase + t) * DI + h * DH + d) = v;
                }
    }

    // GEMM3: H_c = Wt @ X -> g_hc fp32
    {
        float acc[2][8][4];
        #pragma unroll
        for (int i = 0; i < 2; i++)
            #pragma unroll
            for (int j = 0; j < 8; j++)
                #pragma unroll
                for (int f = 0; f < 4; f++) acc[i][j][f] = 0.f;

        #pragma unroll
        for (int ks = 0; ks < 4; ks++) {
            uint32_t a[2][4];
            #pragma unroll
            for (int i = 0; i < 2; i++) {
                int row = wm * 32 + i * 16 + (lane & 15);
                LDM_X4(a[i][0], a[i][1], a[i][2], a[i][3],
                       base + AO_W + (uint32_t)(row * 144 + ks * 32 + (lane >> 4) * 16));
            }
            #pragma unroll
            for (int jj = 0; jj < 4; jj++) {
                int n0 = wn * 64 + jj * 16;
                int grp = lane >> 3, l8 = lane & 7;
                uint32_t addr = base + AO_X
                    + (uint32_t)(ks * 16 + (grp & 1) * 8 + l8) * 528
                    + (uint32_t)(n0 + (grp >> 1) * 8) * 2;
                uint32_t b0, b1, b2, b3;
                LDM_X4T(b0, b1, b2, b3, addr);
                #pragma unroll
                for (int i = 0; i < 2; i++) {
                    MMA16816(acc[i][jj * 2],     a[i][0], a[i][1], a[i][2], a[i][3], b0, b1);
                    MMA16816(acc[i][jj * 2 + 1], a[i][0], a[i][1], a[i][2], a[i][3], b2, b3);
                }
            }
        }
        #pragma unroll
        for (int i = 0; i < 2; i++)
            #pragma unroll
            for (int j8 = 0; j8 < 8; j8++)
                #pragma unroll
                for (int hf = 0; hf < 2; hf++) {
                    int n = wm * 32 + i * 16 + gid + hf * 8;
                    int d = wn * 64 + j8 * 8 + t4 * 2;
                    float2 v = make_float2(acc[i][j8][hf * 2], acc[i][j8][hf * 2 + 1]);
                    *(float2*)(g_hc + (((size_t)bh * NCHKS + chunk) * DS + n) * DH + d) = v;
                }
    }
}

// ---------------- SSD phase B: cross-chunk state recurrence (prefetched) ----
__global__ void __launch_bounds__(256)
state_scan_k()
{
    int dsl = blockIdx.x, h = blockIdx.y, b = blockIdx.z;
    int bh = b * NH + h;
    int tid = threadIdx.x;
    int n = tid >> 2;
    int dbase = dsl * 16 + (tid & 3) * 4;

    float4 hst = make_float4(0.f, 0.f, 0.f, 0.f);
    const size_t cstride = (size_t)DS * DH;
    size_t hb0 = ((size_t)bh * NCHKS * DS + n) * DH + dbase;

    float4 v = *(const float4*)(g_hc + hb0);    // prefetch chunk 0
    for (int c = 0; c < NCHKS; c++) {
        float decay = __expf(g_S[(size_t)bh * TT + c * CHK + CHK - 1]);
        size_t hb = hb0 + (size_t)c * cstride;
        __nv_bfloat162 p0, p1;
        p0.x = __float2bfloat16(hst.x); p0.y = __float2bfloat16(hst.y);
        p1.x = __float2bfloat16(hst.z); p1.y = __float2bfloat16(hst.w);
        *(__nv_bfloat162*)(g_hin + hb) = p0;
        *(__nv_bfloat162*)(g_hin + hb + 2) = p1;

        float4 vn = make_float4(0.f, 0.f, 0.f, 0.f);
        if (c + 1 < NCHKS) vn = *(const float4*)(g_hc + hb + cstride);  // prefetch
        hst.x = decay * hst.x + v.x;
        hst.y = decay * hst.y + v.y;
        hst.z = decay * hst.z + v.z;
        hst.w = decay * hst.w + v.w;
        v = vn;
    }
}

// ---------------- SSD phase C: inter-chunk Y + combine + gate ---------------
#define CO_C 0
#define CO_H 9216
#define CO_S 43008
#define C_SMEM 43264

__global__ void __launch_bounds__(256)
chunk_inter_k(const float* __restrict__ Dp)
{
    extern __shared__ char sm[];
    uint32_t base = smem_u32(sm);
    float* S = (float*)(sm + CO_S);

    int tid = threadIdx.x;
    int wid = tid >> 5, lane = tid & 31;
    int wm = wid >> 2, wn = wid & 3;
    int chunk = blockIdx.x, h = blockIdx.y, b = blockIdx.z;
    int bh = b * NH + h;
    size_t rowbase = (size_t)b * TT + (size_t)chunk * CHK;

    const __nv_bfloat16* csrc = g_bcdt + rowbase * NCATP + 512 + h * 64;
    for (int i = tid; i < 512; i += 256) {
        int r = i >> 3, c = i & 7;
        CP_ASYNC16(base + CO_C + r * 144 + c * 16, csrc + (size_t)r * NCATP + c * 8);
    }
    const __nv_bfloat16* hsrc = g_hin + ((size_t)bh * NCHKS + chunk) * DS * DH;
    for (int i = tid; i < 2048; i += 256) {
        int r = i >> 5, c = i & 31;
        CP_ASYNC16(base + CO_H + r * 528 + c * 16, hsrc + (size_t)r * DH + c * 8);
    }
    if (tid < 64)
        CP_ASYNC4(base + CO_S + tid * 4, g_S + (size_t)bh * TT + chunk * CHK + tid);
    CP_COMMIT();
    CP_WAIT0();
    __syncthreads();

    float acc[2][8][4];
    #pragma unroll
    for (int i = 0; i < 2; i++)
        #pragma unroll
        for (int j = 0; j < 8; j++)
            #pragma unroll
            for (int f = 0; f < 4; f++) acc[i][j][f] = 0.f;

    #pragma unroll
    for (int ks = 0; ks < 4; ks++) {
        uint32_t a[2][4];
        #pragma unroll
        for (int i = 0; i < 2; i++) {
            int row = wm * 32 + i * 16 + (lane & 15);
            LDM_X4(a[i][0], a[i][1], a[i][2], a[i][3],
                   base + CO_C + (uint32_t)(row * 144 + ks * 32 + (lane >> 4) * 16));
        }
        #pragma unroll
        for (int jj = 0; jj < 4; jj++) {
            int n0 = wn * 64 + jj * 16;
            int grp = lane >> 3, l8 = lane & 7;
            uint32_t addr = base + CO_H
                + (uint32_t)(ks * 16 + (grp & 1) * 8 + l8) * 528
                + (uint32_t)(n0 + (grp >> 1) * 8) * 2;
            uint32_t b0, b1, b2, b3;
            LDM_X4T(b0, b1, b2, b3, addr);
            #pragma unroll
            for (int i = 0; i < 2; i++) {
                MMA16816(acc[i][jj * 2],     a[i][0], a[i][1], a[i][2], a[i][3], b0, b1);
                MMA16816(acc[i][jj * 2 + 1], a[i][0], a[i][1], a[i][2], a[i][3], b2, b3);
            }
        }
    }

    float Dh = Dp[h];
    int gid = lane >> 2, t4 = lane & 3;
    #pragma unroll
    for (int i = 0; i < 2; i++)
        #pragma unroll
        for (int j8 = 0; j8 < 8; j8++)
            #pragma unroll
            for (int hf = 0; hf < 2; hf++) {
                int t = wm * 32 + i * 16 + gid + hf * 8;
                int d = wn * 64 + j8 * 8 + t4 * 2;
                float et = __expf(S[t]);
                size_t gi = (rowbase + t) * DI + h * DH + d;
                __nv_bfloat162 yi = *(const __nv_bfloat162*)(g_yi + gi);
                __nv_bfloat162 xv = *(const __nv_bfloat162*)(g_xs + gi);
                __nv_bfloat162 z2 = *(const __nv_bfloat162*)(g_xz + (rowbase + t) * (2 * DI) + DI + h * DH + d);
                float z0 = __bfloat162float(z2.x), z1 = __bfloat162float(z2.y);
                float y0 = acc[i][j8][hf * 2 + 0] * et + __bfloat162float(yi.x) + Dh * __bfloat162float(xv.x);
                float y1 = acc[i][j8][hf * 2 + 1] * et + __bfloat162float(yi.y) + Dh * __bfloat162float(xv.y);
                float s0 = z0 / (1.f + __expf(-z0));
                float s1 = z1 / (1.f + __expf(-z1));
                __nv_bfloat162 o;
                o.x = __float2bfloat16(y0 * s0);
                o.y = __float2bfloat16(y1 * s1);
                *(__nv_bfloat162*)(g_y + gi) = o;
            }
}

// ---------------- launch ----------------------------------------------------
extern "C" void kernel_launch(void* const* d_in, const int* in_sizes, int n_in,
                              void* d_out, int out_size)
{
    const float* x      = (const float*)d_in[0];
    const float* norm_w = (const float*)d_in[1];
    const float* in_w   = (const float*)d_in[2];
    const float* conv_w = (const float*)d_in[3];
    const float* conv_b = (const float*)d_in[4];
    const float* A_log  = (const float*)d_in[5];
    const float* B_w    = (const float*)d_in[6];
    const float* C_w    = (const float*)d_in[7];
    const float* dt_w   = (const float*)d_in[8];
    const float* dt_b   = (const float*)d_in[9];
    const float* Dp     = (const float*)d_in[10];
    const float* out_w  = (const float*)d_in[11];
    float* out = (float*)d_out;

    __nv_bfloat16 *p_xn, *p_xs, *p_y, *p_inw, *p_wcat, *p_outw, *p_bcdt, *p_xz;
    cudaGetSymbolAddress((void**)&p_xn, g_xn);
    cudaGetSymbolAddress((void**)&p_xz, g_xz);
    cudaGetSymbolAddress((void**)&p_xs, g_xs);
    cudaGetSymbolAddress((void**)&p_bcdt, g_bcdt);
    cudaGetSymbolAddress((void**)&p_y, g_y);
    cudaGetSymbolAddress((void**)&p_inw, g_inw);
    cudaGetSymbolAddress((void**)&p_wcat, g_wcat);
    cudaGetSymbolAddress((void**)&p_outw, g_outw);

    cudaFuncSetAttribute(gemm_mma<false, true>,  cudaFuncAttributeMaxDynamicSharedMemorySize, GEMM_SMEM);
    cudaFuncSetAttribute(gemm_mma<true, false>,  cudaFuncAttributeMaxDynamicSharedMemorySize, GEMM_SMEM);
    cudaFuncSetAttribute(chunk_intra_k, cudaFuncAttributeMaxDynamicSharedMemorySize, A_SMEM);
    cudaFuncSetAttribute(chunk_inter_k, cudaFuncAttributeMaxDynamicSharedMemorySize, C_SMEM);

    // [0] in_w -> bf16
    cvt_bf16_k<<<256, 256>>>((const float4*)in_w, (__nv_bfloat162*)p_inw, 2 * DI * DM / 4);
    // [1] RMSNorm -> bf16
    rmsnorm_k<<<NROWS, 256>>>(x, norm_w);
    // [2] out_w -> bf16 + fused [B|C|dt] weight (merged)
    prep2_k<<<256, 256>>>(out_w, B_w, C_w, dt_w);
    // [3] xz = xn @ in_w^T -> bf16  (ncu capture slot)
    gemm_mma<false, true><<<dim3(4096 / BN, NROWS / BM), 256, GEMM_SMEM>>>(
        p_xn, p_inw, (void*)p_xz, nullptr, NROWS, 2 * DI, DM);
    // [4] causal conv + SiLU -> bf16
    conv_silu_k<<<dim3(DI / 256, TT / 4, BSZ), 256>>>(conv_w, conv_b);
    // [5] [B | C | dt] = xs @ wcat^T -> bf16
    gemm_mma<false, true><<<dim3(NCATP / BN, NROWS / BM), 256, GEMM_SMEM>>>(
        p_xs, p_wcat, (void*)p_bcdt, nullptr, NROWS, NCATP, DI);
    // [6] SSD phase A
    chunk_intra_k<<<dim3(NCHKS, NH, BSZ), 256, A_SMEM>>>(A_log, dt_b);
    // [7] SSD phase B (prefetched, 256 CTAs)
    state_scan_k<<<dim3(16, NH, BSZ), 256>>>();
    // [8] SSD phase C
    chunk_inter_k<<<dim3(NCHKS, NH, BSZ), 256, C_SMEM>>>(Dp);
    // [9] out = y @ out_w^T + residual
    gemm_mma<true, false><<<dim3(1024 / BN, NROWS / BM), 256, GEMM_SMEM>>>(
        p_y, p_outw, (void*)out, x, NROWS, DM, DI);
}

// round 15
// speedup vs baseline: 1.1315x; 1.0302x over previous
#include <cuda_runtime.h>
#include <cuda_bf16.h>
#include <math.h>
#include <stdint.h>

// ---------------- problem constants ----------------------------------------
#define BSZ 2
#define TT 2048
#define DM 1024
#define DI 2048
#define NH 8
#define DS 64
#define DH 256
#define NROWS (BSZ*TT)          // 4096
#define EPSV 1e-6f
#define NCATP 1152              // B(512) | C(512) | dt(8) | pad -> 9*128
#define CHK 64
#define NCHKS (TT/CHK)          // 32

// ---------------- scratch (device globals) ---------------------------------
__device__ __nv_bfloat16 g_xn[(size_t)NROWS * DM];
__device__ __nv_bfloat16 g_xz[(size_t)NROWS * 2 * DI];
__device__ __nv_bfloat16 g_xs[(size_t)NROWS * DI];
__device__ __nv_bfloat16 g_bcdt[(size_t)NROWS * NCATP];
__device__ __nv_bfloat16 g_y [(size_t)NROWS * DI];
__device__ __nv_bfloat16 g_yi[(size_t)NROWS * DI];
__device__ float         g_hc [(size_t)16 * NCHKS * DS * DH];
__device__ __nv_bfloat16 g_hin[(size_t)16 * NCHKS * DS * DH];
__device__ float         g_S  [(size_t)16 * TT];
__device__ __nv_bfloat16 g_inw [(size_t)(2*DI) * DM];
__device__ __nv_bfloat16 g_wcat[(size_t)NCATP * DI];
__device__ __nv_bfloat16 g_outw[(size_t)DM * DI];

// ---------------- PTX helpers ----------------------------------------------
__device__ __forceinline__ uint32_t smem_u32(const void* p) {
    uint32_t a;
    asm("{ .reg .u64 t; cvta.to.shared.u64 t, %1; cvt.u32.u64 %0, t; }" : "=r"(a) : "l"(p));
    return a;
}

#define CP_ASYNC16(dst, src) \
    asm volatile("cp.async.cg.shared.global [%0], [%1], 16;" :: "r"(dst), "l"(src) : "memory")
#define CP_ASYNC4(dst, src) \
    asm volatile("cp.async.ca.shared.global [%0], [%1], 4;" :: "r"(dst), "l"(src) : "memory")
#define CP_COMMIT() asm volatile("cp.async.commit_group;" ::: "memory")
#define CP_WAIT1()  asm volatile("cp.async.wait_group 1;" ::: "memory")
#define CP_WAIT0()  asm volatile("cp.async.wait_group 0;" ::: "memory")

#define LDM_X4(r0, r1, r2, r3, addr) \
    asm volatile("ldmatrix.sync.aligned.m8n8.x4.shared.b16 {%0,%1,%2,%3}, [%4];" \
                 : "=r"(r0), "=r"(r1), "=r"(r2), "=r"(r3) : "r"(addr))
#define LDM_X4T(r0, r1, r2, r3, addr) \
    asm volatile("ldmatrix.sync.aligned.m8n8.x4.trans.shared.b16 {%0,%1,%2,%3}, [%4];" \
                 : "=r"(r0), "=r"(r1), "=r"(r2), "=r"(r3) : "r"(addr))
#define LDM_X2(r0, r1, addr) \
    asm volatile("ldmatrix.sync.aligned.m8n8.x2.shared.b16 {%0,%1}, [%2];" \
                 : "=r"(r0), "=r"(r1) : "r"(addr))

#define MMA16816(d, a0, a1, a2, a3, b0, b1) \
    asm volatile("mma.sync.aligned.m16n8k16.row.col.f32.bf16.bf16.f32 " \
                 "{%0,%1,%2,%3}, {%4,%5,%6,%7}, {%8,%9}, {%0,%1,%2,%3};" \
                 : "+f"((d)[0]), "+f"((d)[1]), "+f"((d)[2]), "+f"((d)[3]) \
                 : "r"(a0), "r"(a1), "r"(a2), "r"(a3), "r"(b0), "r"(b1))

// ---------------- bf16 mma.sync GEMM: C[M,N] = A[M,K] @ W[N,K]^T (+Res) ----
#define BM 128
#define BN 128
#define BK64 64
#define ROWB 144
#define SA_BYTES (BM * ROWB)
#define STG_BYTES (2 * SA_BYTES)
#define NST 3
#define GEMM_SMEM (NST * STG_BYTES)      // 110592

template <bool ADD_RES, bool OUT_BF16>
__global__ void __launch_bounds__(256)
gemm_mma(const __nv_bfloat16* __restrict__ A, const __nv_bfloat16* __restrict__ W,
         void* __restrict__ Cout, const float* __restrict__ Res,
         int M, int N, int K)
{
    extern __shared__ char sm[];
    uint32_t base = smem_u32(sm);

    int tid = threadIdx.x;
    int wid = tid >> 5, lane = tid & 31;
    int wm = wid >> 2, wn = wid & 3;
    int m0 = blockIdx.y * BM;
    int n0 = blockIdx.x * BN;

    const __nv_bfloat16* Ag = A + (size_t)m0 * K;
    const __nv_bfloat16* Wg = W + (size_t)n0 * K;

    float acc[4][4][4];
    #pragma unroll
    for (int i = 0; i < 4; i++)
        #pragma unroll
        for (int j = 0; j < 4; j++)
            #pragma unroll
            for (int f = 0; f < 4; f++) acc[i][j][f] = 0.f;

    int nk = K / BK64;

    auto load_stage = [&](int s, int k0) {
        uint32_t sA = base + s * STG_BYTES;
        uint32_t sB = sA + SA_BYTES;
        #pragma unroll
        for (int it = 0; it < 4; it++) {
            int i = tid + it * 256;
            int r = i >> 3, c = i & 7;
            CP_ASYNC16(sA + r * ROWB + c * 16, Ag + (size_t)r * K + k0 + c * 8);
        }
        #pragma unroll
        for (int it = 0; it < 4; it++) {
            int i = tid + it * 256;
            int r = i >> 3, c = i & 7;
            CP_ASYNC16(sB + r * ROWB + c * 16, Wg + (size_t)r * K + k0 + c * 8);
        }
    };

    load_stage(0, 0);      CP_COMMIT();
    load_stage(1, BK64);   CP_COMMIT();

    int stg = 0;
    for (int kt = 0; kt < nk; kt++) {
        CP_WAIT1();
        __syncthreads();

        int s2 = stg + 2; if (s2 >= NST) s2 -= NST;
        if (kt + 2 < nk) load_stage(s2, (kt + 2) * BK64);
        CP_COMMIT();

        uint32_t sA = base + stg * STG_BYTES;
        uint32_t sB = sA + SA_BYTES;

        #pragma unroll
        for (int ks = 0; ks < 4; ks++) {
            int colA = ks * 32 + (lane >> 4) * 16;
            int colB = ks * 32 + ((lane >> 3) & 1) * 16;
            uint32_t a[4][4], b[4][2];
            #pragma unroll
            for (int i = 0; i < 4; i++) {
                int row = wm * 64 + i * 16 + (lane & 15);
                LDM_X4(a[i][0], a[i][1], a[i][2], a[i][3],
                       sA + (uint32_t)(row * ROWB + colA));
            }
            #pragma unroll
            for (int j = 0; j < 4; j++) {
                int row = wn * 32 + j * 8 + (lane & 7);
                LDM_X2(b[j][0], b[j][1],
                       sB + (uint32_t)(row * ROWB + colB));
            }
            #pragma unroll
            for (int i = 0; i < 4; i++)
                #pragma unroll
                for (int j = 0; j < 4; j++)
                    MMA16816(acc[i][j], a[i][0], a[i][1], a[i][2], a[i][3],
                             b[j][0], b[j][1]);
        }
        stg++; if (stg >= NST) stg -= NST;
    }

    int gid = lane >> 2, t4 = lane & 3;
    #pragma unroll
    for (int i = 0; i < 4; i++) {
        int row0 = m0 + wm * 64 + i * 16 + gid;
        #pragma unroll
        for (int j = 0; j < 4; j++) {
            int col = n0 + wn * 32 + j * 8 + t4 * 2;
            size_t i0 = (size_t)row0 * N + col;
            size_t i1 = (size_t)(row0 + 8) * N + col;
            float2 v0 = make_float2(acc[i][j][0], acc[i][j][1]);
            float2 v1 = make_float2(acc[i][j][2], acc[i][j][3]);
            if (ADD_RES) {
                float2 r0 = *(const float2*)(Res + i0);
                float2 r1 = *(const float2*)(Res + i1);
                v0.x += r0.x; v0.y += r0.y;
                v1.x += r1.x; v1.y += r1.y;
            }
            if (OUT_BF16) {
                __nv_bfloat16* Cb = (__nv_bfloat16*)Cout;
                __nv_bfloat162 o0, o1;
                o0.x = __float2bfloat16(v0.x); o0.y = __float2bfloat16(v0.y);
                o1.x = __float2bfloat16(v1.x); o1.y = __float2bfloat16(v1.y);
                *(__nv_bfloat162*)(Cb + i0) = o0;
                *(__nv_bfloat162*)(Cb + i1) = o1;
            } else {
                float* Cf = (float*)Cout;
                *(float2*)(Cf + i0) = v0;
                *(float2*)(Cf + i1) = v1;
            }
        }
    }
}

// ---------------- all weight prep in one kernel -----------------------------
__global__ void prep_all_k(const float* __restrict__ in_w, const float* __restrict__ out_w,
                           const float* __restrict__ Bw, const float* __restrict__ Cw,
                           const float* __restrict__ dtw)
{
    const int N1 = 2 * DI * DM / 4;      // 2097152 (in_w)
    const int N2 = DM * DI / 4;          // 524288  (out_w)
    const int N3 = NCATP * DI / 4;       // 589824  (wcat)
    for (int idx = blockIdx.x * 256 + threadIdx.x; idx < N1 + N2 + N3; idx += gridDim.x * 256) {
        float4 v;
        __nv_bfloat162* dst;
        if (idx < N1) {
            v = ((const float4*)in_w)[idx];
            dst = (__nv_bfloat162*)g_inw + 2 * idx;
        } else if (idx < N1 + N2) {
            int i = idx - N1;
            v = ((const float4*)out_w)[i];
            dst = (__nv_bfloat162*)g_outw + 2 * i;
        } else {
            int i = idx - N1 - N2;
            int r = i >> 9;
            int kk = (i & 511) * 4;
            if (r < 512)       v = *(const float4*)(Bw + (size_t)r * DI + kk);
            else if (r < 1024) v = *(const float4*)(Cw + (size_t)(r - 512) * DI + kk);
            else if (r < 1032) v = *(const float4*)(dtw + (size_t)(r - 1024) * DI + kk);
            else               v = make_float4(0.f, 0.f, 0.f, 0.f);
            dst = (__nv_bfloat162*)g_wcat + 2 * i;
        }
        __nv_bfloat162 o0, o1;
        o0.x = __float2bfloat16(v.x); o0.y = __float2bfloat16(v.y);
        o1.x = __float2bfloat16(v.z); o1.y = __float2bfloat16(v.w);
        dst[0] = o0; dst[1] = o1;
    }
}

// ---------------- RMSNorm (float4, writes bf16) -----------------------------
__global__ void rmsnorm_k(const float* __restrict__ x, const float* __restrict__ w)
{
    int row = blockIdx.x;
    int tid = threadIdx.x;
    const float4* xr = (const float4*)(x + (size_t)row * DM);
    float4 v = xr[tid];
    float s = v.x * v.x + v.y * v.y + v.z * v.z + v.w * v.w;
    __shared__ float red[8];
    #pragma unroll
    for (int o = 16; o; o >>= 1) s += __shfl_xor_sync(0xffffffffu, s, o);
    if ((tid & 31) == 0) red[tid >> 5] = s;
    __syncthreads();
    if (tid < 8) {
        float t = red[tid];
        #pragma unroll
        for (int o = 4; o; o >>= 1) t += __shfl_xor_sync(0xffu, t, o);
        if (tid == 0) red[0] = rsqrtf(t / (float)DM + EPSV);
    }
    __syncthreads();
    float sc = red[0];
    float4 wv = ((const float4*)w)[tid];
    __nv_bfloat162 o0, o1;
    o0.x = __float2bfloat16(v.x * sc * wv.x);
    o0.y = __float2bfloat16(v.y * sc * wv.y);
    o1.x = __float2bfloat16(v.z * sc * wv.z);
    o1.y = __float2bfloat16(v.w * sc * wv.w);
    __nv_bfloat162* orow = (__nv_bfloat162*)(g_xn + (size_t)row * DM);
    orow[tid * 2] = o0;
    orow[tid * 2 + 1] = o1;
}

// ---------------- causal depthwise conv (K=4) + bias + SiLU -> bf16 ---------
__global__ void conv_silu_k(const float* __restrict__ cw, const float* __restrict__ cb)
{
    int c = blockIdx.x * 256 + threadIdx.x;
    int t0 = blockIdx.y * 4;
    int b = blockIdx.z;
    float4 w = ((const float4*)cw)[c];
    float bias = cb[c];
    size_t colbase = (size_t)b * TT * (2 * DI) + c;
    const size_t stride = 2 * DI;

    float xv[7];
    #pragma unroll
    for (int k = 0; k < 7; k++) {
        int t = t0 - 3 + k;
        xv[k] = (t >= 0) ? __bfloat162float(g_xz[colbase + (size_t)t * stride]) : 0.f;
    }
    size_t obase = ((size_t)b * TT + t0) * DI + c;
    #pragma unroll
    for (int i = 0; i < 4; i++) {
        float acc = bias + w.x * xv[i] + w.y * xv[i + 1] + w.z * xv[i + 2] + w.w * xv[i + 3];
        float sig = 1.f / (1.f + __expf(-acc));
        g_xs[obase + (size_t)i * DI] = __float2bfloat16(acc * sig);
    }
}

// ---------------- SSD phase A: intra-chunk + state contributions ------------
// Y_intra now includes the D*x skip term (X is already in smem).
#define AO_C 0
#define AO_B 9216
#define AO_P 18432
#define AO_W 27648
#define AO_X 36864
#define AO_S 70656
#define AO_DT 70912
#define AO_WJ 71168
#define A_SMEM 71424

__global__ void __launch_bounds__(256)
chunk_intra_k(const float* __restrict__ A_log, const float* __restrict__ dtb,
              const float* __restrict__ Dp)
{
    extern __shared__ char sm[];
    uint32_t base = smem_u32(sm);
    float* S  = (float*)(sm + AO_S);
    float* DT = (float*)(sm + AO_DT);
    float* WJ = (float*)(sm + AO_WJ);

    int tid = threadIdx.x;
    int wid = tid >> 5, lane = tid & 31;
    int wm = wid >> 2, wn = wid & 3;
    int chunk = blockIdx.x, h = blockIdx.y, b = blockIdx.z;
    int bh = b * NH + h;
    size_t rowbase = (size_t)b * TT + (size_t)chunk * CHK;

    const __nv_bfloat16* bsrc = g_bcdt + rowbase * NCATP + h * 64;
    for (int i = tid; i < 512; i += 256) {
        int r = i >> 3, c = i & 7;
        CP_ASYNC16(base + AO_B + r * 144 + c * 16, bsrc + (size_t)r * NCATP + c * 8);
        CP_ASYNC16(base + AO_C + r * 144 + c * 16, bsrc + (size_t)r * NCATP + 512 + c * 8);
    }
    for (int i = tid; i < 2048; i += 256) {
        int r = i >> 5, c = i & 31;
        CP_ASYNC16(base + AO_X + r * 528 + c * 16, g_xs + (rowbase + r) * DI + h * DH + c * 8);
    }
    CP_COMMIT();

    if (tid < 64) {
        float v = __bfloat162float(g_bcdt[(rowbase + tid) * NCATP + 1024 + h]) + dtb[h];
        DT[tid] = (v > 20.f) ? v : log1pf(expf(v));
    }
    CP_WAIT0();
    __syncthreads();

    float Ah = -__expf(A_log[h]);
    if (wid == 0) {
        float a0 = DT[lane] * Ah, a1 = DT[lane + 32] * Ah;
        #pragma unroll
        for (int off = 1; off < 32; off <<= 1) {
            float u0 = __shfl_up_sync(0xffffffffu, a0, off);
            float u1 = __shfl_up_sync(0xffffffffu, a1, off);
            if (lane >= off) { a0 += u0; a1 += u1; }
        }
        float tot = __shfl_sync(0xffffffffu, a0, 31);
        a1 += tot;
        S[lane] = a0; S[lane + 32] = a1;
    }
    __syncthreads();
    if (tid < 64) WJ[tid] = __expf(S[63] - S[tid]) * DT[tid];

    // GEMM1: G = C @ B^T
    float acc1[2][2][4];
    #pragma unroll
    for (int i = 0; i < 2; i++)
        #pragma unroll
        for (int j = 0; j < 2; j++)
            #pragma unroll
            for (int f = 0; f < 4; f++) acc1[i][j][f] = 0.f;

    #pragma unroll
    for (int ks = 0; ks < 4; ks++) {
        uint32_t a[2][4], bb[4];
        #pragma unroll
        for (int i = 0; i < 2; i++) {
            int row = wm * 32 + i * 16 + (lane & 15);
            LDM_X4(a[i][0], a[i][1], a[i][2], a[i][3],
                   base + AO_C + (uint32_t)(row * 144 + ks * 32 + (lane >> 4) * 16));
        }
        {
            int row = wn * 16 + (lane & 15);
            LDM_X4(bb[0], bb[1], bb[2], bb[3],
                   base + AO_B + (uint32_t)(row * 144 + ks * 32 + (lane >> 4) * 16));
        }
        #pragma unroll
        for (int i = 0; i < 2; i++) {
            MMA16816(acc1[i][0], a[i][0], a[i][1], a[i][2], a[i][3], bb[0], bb[2]);
            MMA16816(acc1[i][1], a[i][0], a[i][1], a[i][2], a[i][3], bb[1], bb[3]);
        }
    }

    int gid = lane >> 2, t4 = lane & 3;
    #pragma unroll
    for (int i = 0; i < 2; i++) {
        #pragma unroll
        for (int jd = 0; jd < 2; jd++) {
            int j0 = wn * 16 + jd * 8 + t4 * 2;
            #pragma unroll
            for (int hf = 0; hf < 2; hf++) {
                int t = wm * 32 + i * 16 + gid + hf * 8;
                float v0 = acc1[i][jd][hf * 2 + 0];
                float v1 = acc1[i][jd][hf * 2 + 1];
                float p0 = (t >= j0)     ? v0 * __expf(S[t] - S[j0])     * DT[j0]     : 0.f;
                float p1 = (t >= j0 + 1) ? v1 * __expf(S[t] - S[j0 + 1]) * DT[j0 + 1] : 0.f;
                __nv_bfloat162 pr;
                pr.x = __float2bfloat16(p0); pr.y = __float2bfloat16(p1);
                *(__nv_bfloat162*)(sm + AO_P + t * 144 + j0 * 2) = pr;
            }
        }
    }
    if (tid < 64) g_S[(size_t)bh * TT + chunk * CHK + tid] = S[tid];
    __syncthreads();

    for (int idx = tid; idx < 4096; idx += 256) {
        int j = idx >> 6, n = idx & 63;
        float bv = __bfloat162float(*(const __nv_bfloat16*)(sm + AO_B + j * 144 + n * 2));
        *(__nv_bfloat16*)(sm + AO_W + n * 144 + j * 2) = __float2bfloat16(bv * WJ[j]);
    }
    __syncthreads();

    float Dh = Dp[h];

    // GEMM2: Y_intra + D*x -> g_yi (bf16)
    {
        float acc[2][8][4];
        #pragma unroll
        for (int i = 0; i < 2; i++)
            #pragma unroll
            for (int j = 0; j < 8; j++)
                #pragma unroll
                for (int f = 0; f < 4; f++) acc[i][j][f] = 0.f;

        #pragma unroll
        for (int ks = 0; ks < 4; ks++) {
            uint32_t a[2][4];
            #pragma unroll
            for (int i = 0; i < 2; i++) {
                int row = wm * 32 + i * 16 + (lane & 15);
                LDM_X4(a[i][0], a[i][1], a[i][2], a[i][3],
                       base + AO_P + (uint32_t)(row * 144 + ks * 32 + (lane >> 4) * 16));
            }
            #pragma unroll
            for (int jj = 0; jj < 4; jj++) {
                int n0 = wn * 64 + jj * 16;
                int grp = lane >> 3, l8 = lane & 7;
                uint32_t addr = base + AO_X
                    + (uint32_t)(ks * 16 + (grp & 1) * 8 + l8) * 528
                    + (uint32_t)(n0 + (grp >> 1) * 8) * 2;
                uint32_t b0, b1, b2, b3;
                LDM_X4T(b0, b1, b2, b3, addr);
                #pragma unroll
                for (int i = 0; i < 2; i++) {
                    MMA16816(acc[i][jj * 2],     a[i][0], a[i][1], a[i][2], a[i][3], b0, b1);
                    MMA16816(acc[i][jj * 2 + 1], a[i][0], a[i][1], a[i][2], a[i][3], b2, b3);
                }
            }
        }
        #pragma unroll
        for (int i = 0; i < 2; i++)
            #pragma unroll
            for (int j8 = 0; j8 < 8; j8++)
                #pragma unroll
                for (int hf = 0; hf < 2; hf++) {
                    int t = wm * 32 + i * 16 + gid + hf * 8;
                    int d = wn * 64 + j8 * 8 + t4 * 2;
                    __nv_bfloat162 xv2 = *(const __nv_bfloat162*)(sm + AO_X + (uint32_t)(t * 528 + d * 2));
                    __nv_bfloat162 v;
                    v.x = __float2bfloat16(acc[i][j8][hf * 2]     + Dh * __bfloat162float(xv2.x));
                    v.y = __float2bfloat16(acc[i][j8][hf * 2 + 1] + Dh * __bfloat162float(xv2.y));
                    *(__nv_bfloat162*)(g_yi + (rowbase + t) * DI + h * DH + d) = v;
                }
    }

    // GEMM3: H_c = Wt @ X -> g_hc fp32
    {
        float acc[2][8][4];
        #pragma unroll
        for (int i = 0; i < 2; i++)
            #pragma unroll
            for (int j = 0; j < 8; j++)
                #pragma unroll
                for (int f = 0; f < 4; f++) acc[i][j][f] = 0.f;

        #pragma unroll
        for (int ks = 0; ks < 4; ks++) {
            uint32_t a[2][4];
            #pragma unroll
            for (int i = 0; i < 2; i++) {
                int row = wm * 32 + i * 16 + (lane & 15);
                LDM_X4(a[i][0], a[i][1], a[i][2], a[i][3],
                       base + AO_W + (uint32_t)(row * 144 + ks * 32 + (lane >> 4) * 16));
            }
            #pragma unroll
            for (int jj = 0; jj < 4; jj++) {
                int n0 = wn * 64 + jj * 16;
                int grp = lane >> 3, l8 = lane & 7;
                uint32_t addr = base + AO_X
                    + (uint32_t)(ks * 16 + (grp & 1) * 8 + l8) * 528
                    + (uint32_t)(n0 + (grp >> 1) * 8) * 2;
                uint32_t b0, b1, b2, b3;
                LDM_X4T(b0, b1, b2, b3, addr);
                #pragma unroll
                for (int i = 0; i < 2; i++) {
                    MMA16816(acc[i][jj * 2],     a[i][0], a[i][1], a[i][2], a[i][3], b0, b1);
                    MMA16816(acc[i][jj * 2 + 1], a[i][0], a[i][1], a[i][2], a[i][3], b2, b3);
                }
            }
        }
        #pragma unroll
        for (int i = 0; i < 2; i++)
            #pragma unroll
            for (int j8 = 0; j8 < 8; j8++)
                #pragma unroll
                for (int hf = 0; hf < 2; hf++) {
                    int n = wm * 32 + i * 16 + gid + hf * 8;
                    int d = wn * 64 + j8 * 8 + t4 * 2;
                    float2 v = make_float2(acc[i][j8][hf * 2], acc[i][j8][hf * 2 + 1]);
                    *(float2*)(g_hc + (((size_t)bh * NCHKS + chunk) * DS + n) * DH + d) = v;
                }
    }
}

// ---------------- SSD phase B: cross-chunk state recurrence (prefetched) ----
__global__ void __launch_bounds__(256)
state_scan_k()
{
    int dsl = blockIdx.x, h = blockIdx.y, b = blockIdx.z;
    int bh = b * NH + h;
    int tid = threadIdx.x;
    int n = tid >> 2;
    int dbase = dsl * 16 + (tid & 3) * 4;

    float4 hst = make_float4(0.f, 0.f, 0.f, 0.f);
    const size_t cstride = (size_t)DS * DH;
    size_t hb0 = ((size_t)bh * NCHKS * DS + n) * DH + dbase;

    float4 v = *(const float4*)(g_hc + hb0);
    for (int c = 0; c < NCHKS; c++) {
        float decay = __expf(g_S[(size_t)bh * TT + c * CHK + CHK - 1]);
        size_t hb = hb0 + (size_t)c * cstride;
        __nv_bfloat162 p0, p1;
        p0.x = __float2bfloat16(hst.x); p0.y = __float2bfloat16(hst.y);
        p1.x = __float2bfloat16(hst.z); p1.y = __float2bfloat16(hst.w);
        *(__nv_bfloat162*)(g_hin + hb) = p0;
        *(__nv_bfloat162*)(g_hin + hb + 2) = p1;

        float4 vn = make_float4(0.f, 0.f, 0.f, 0.f);
        if (c + 1 < NCHKS) vn = *(const float4*)(g_hc + hb + cstride);
        hst.x = decay * hst.x + v.x;
        hst.y = decay * hst.y + v.y;
        hst.z = decay * hst.z + v.z;
        hst.w = decay * hst.w + v.w;
        v = vn;
    }
}

// ---------------- SSD phase C: inter-chunk Y + combine + gate ---------------
#define CO_C 0
#define CO_H 9216
#define CO_S 43008
#define C_SMEM 43264

__global__ void __launch_bounds__(256)
chunk_inter_k()
{
    extern __shared__ char sm[];
    uint32_t base = smem_u32(sm);
    float* S = (float*)(sm + CO_S);

    int tid = threadIdx.x;
    int wid = tid >> 5, lane = tid & 31;
    int wm = wid >> 2, wn = wid & 3;
    int chunk = blockIdx.x, h = blockIdx.y, b = blockIdx.z;
    int bh = b * NH + h;
    size_t rowbase = (size_t)b * TT + (size_t)chunk * CHK;

    const __nv_bfloat16* csrc = g_bcdt + rowbase * NCATP + 512 + h * 64;
    for (int i = tid; i < 512; i += 256) {
        int r = i >> 3, c = i & 7;
        CP_ASYNC16(base + CO_C + r * 144 + c * 16, csrc + (size_t)r * NCATP + c * 8);
    }
    const __nv_bfloat16* hsrc = g_hin + ((size_t)bh * NCHKS + chunk) * DS * DH;
    for (int i = tid; i < 2048; i += 256) {
        int r = i >> 5, c = i & 31;
        CP_ASYNC16(base + CO_H + r * 528 + c * 16, hsrc + (size_t)r * DH + c * 8);
    }
    if (tid < 64)
        CP_ASYNC4(base + CO_S + tid * 4, g_S + (size_t)bh * TT + chunk * CHK + tid);
    CP_COMMIT();
    CP_WAIT0();
    __syncthreads();

    float acc[2][8][4];
    #pragma unroll
    for (int i = 0; i < 2; i++)
        #pragma unroll
        for (int j = 0; j < 8; j++)
            #pragma unroll
            for (int f = 0; f < 4; f++) acc[i][j][f] = 0.f;

    #pragma unroll
    for (int ks = 0; ks < 4; ks++) {
        uint32_t a[2][4];
        #pragma unroll
        for (int i = 0; i < 2; i++) {
            int row = wm * 32 + i * 16 + (lane & 15);
            LDM_X4(a[i][0], a[i][1], a[i][2], a[i][3],
                   base + CO_C + (uint32_t)(row * 144 + ks * 32 + (lane >> 4) * 16));
        }
        #pragma unroll
        for (int jj = 0; jj < 4; jj++) {
            int n0 = wn * 64 + jj * 16;
            int grp = lane >> 3, l8 = lane & 7;
            uint32_t addr = base + CO_H
                + (uint32_t)(ks * 16 + (grp & 1) * 8 + l8) * 528
                + (uint32_t)(n0 + (grp >> 1) * 8) * 2;
            uint32_t b0, b1, b2, b3;
            LDM_X4T(b0, b1, b2, b3, addr);
            #pragma unroll
            for (int i = 0; i < 2; i++) {
                MMA16816(acc[i][jj * 2],     a[i][0], a[i][1], a[i][2], a[i][3], b0, b1);
                MMA16816(acc[i][jj * 2 + 1], a[i][0], a[i][1], a[i][2], a[i][3], b2, b3);
            }
        }
    }

    int gid = lane >> 2, t4 = lane & 3;
    #pragma unroll
    for (int i = 0; i < 2; i++)
        #pragma unroll
        for (int j8 = 0; j8 < 8; j8++)
            #pragma unroll
            for (int hf = 0; hf < 2; hf++) {
                int t = wm * 32 + i * 16 + gid + hf * 8;
                int d = wn * 64 + j8 * 8 + t4 * 2;
                float et = __expf(S[t]);
                size_t gi = (rowbase + t) * DI + h * DH + d;
                __nv_bfloat162 yi = *(const __nv_bfloat162*)(g_yi + gi);
                __nv_bfloat162 z2 = *(const __nv_bfloat162*)(g_xz + (rowbase + t) * (2 * DI) + DI + h * DH + d);
                float z0 = __bfloat162float(z2.x), z1 = __bfloat162float(z2.y);
                float y0 = acc[i][j8][hf * 2 + 0] * et + __bfloat162float(yi.x);
                float y1 = acc[i][j8][hf * 2 + 1] * et + __bfloat162float(yi.y);
                float s0 = z0 / (1.f + __expf(-z0));
                float s1 = z1 / (1.f + __expf(-z1));
                __nv_bfloat162 o;
                o.x = __float2bfloat16(y0 * s0);
                o.y = __float2bfloat16(y1 * s1);
                *(__nv_bfloat162*)(g_y + gi) = o;
            }
}

// ---------------- launch ----------------------------------------------------
extern "C" void kernel_launch(void* const* d_in, const int* in_sizes, int n_in,
                              void* d_out, int out_size)
{
    const float* x      = (const float*)d_in[0];
    const float* norm_w = (const float*)d_in[1];
    const float* in_w   = (const float*)d_in[2];
    const float* conv_w = (const float*)d_in[3];
    const float* conv_b = (const float*)d_in[4];
    const float* A_log  = (const float*)d_in[5];
    const float* B_w    = (const float*)d_in[6];
    const float* C_w    = (const float*)d_in[7];
    const float* dt_w   = (const float*)d_in[8];
    const float* dt_b   = (const float*)d_in[9];
    const float* Dp     = (const float*)d_in[10];
    const float* out_w  = (const float*)d_in[11];
    float* out = (float*)d_out;

    __nv_bfloat16 *p_xn, *p_xs, *p_y, *p_inw, *p_wcat, *p_outw, *p_bcdt, *p_xz;
    cudaGetSymbolAddress((void**)&p_xn, g_xn);
    cudaGetSymbolAddress((void**)&p_xz, g_xz);
    cudaGetSymbolAddress((void**)&p_xs, g_xs);
    cudaGetSymbolAddress((void**)&p_bcdt, g_bcdt);
    cudaGetSymbolAddress((void**)&p_y, g_y);
    cudaGetSymbolAddress((void**)&p_inw, g_inw);
    cudaGetSymbolAddress((void**)&p_wcat, g_wcat);
    cudaGetSymbolAddress((void**)&p_outw, g_outw);

    cudaFuncSetAttribute(gemm_mma<false, true>,  cudaFuncAttributeMaxDynamicSharedMemorySize, GEMM_SMEM);
    cudaFuncSetAttribute(gemm_mma<true, false>,  cudaFuncAttributeMaxDynamicSharedMemorySize, GEMM_SMEM);
    cudaFuncSetAttribute(chunk_intra_k, cudaFuncAttributeMaxDynamicSharedMemorySize, A_SMEM);
    cudaFuncSetAttribute(chunk_inter_k, cudaFuncAttributeMaxDynamicSharedMemorySize, C_SMEM);

    // [0] all weights -> bf16 (in_w + out_w + wcat, one kernel)
    prep_all_k<<<512, 256>>>(in_w, out_w, B_w, C_w, dt_w);
    // [1] RMSNorm -> bf16
    rmsnorm_k<<<NROWS, 256>>>(x, norm_w);
    // [2] xz = xn @ in_w^T -> bf16
    gemm_mma<false, true><<<dim3(4096 / BN, NROWS / BM), 256, GEMM_SMEM>>>(
        p_xn, p_inw, (void*)p_xz, nullptr, NROWS, 2 * DI, DM);
    // [3] causal conv + SiLU -> bf16  (ncu capture slot)
    conv_silu_k<<<dim3(DI / 256, TT / 4, BSZ), 256>>>(conv_w, conv_b);
    // [4] [B | C | dt] = xs @ wcat^T -> bf16
    gemm_mma<false, true><<<dim3(NCATP / BN, NROWS / BM), 256, GEMM_SMEM>>>(
        p_xs, p_wcat, (void*)p_bcdt, nullptr, NROWS, NCATP, DI);
    // [5] SSD phase A (+ D*x fused into Y_intra)
    chunk_intra_k<<<dim3(NCHKS, NH, BSZ), 256, A_SMEM>>>(A_log, dt_b, Dp);
    // [6] SSD phase B
    state_scan_k<<<dim3(16, NH, BSZ), 256>>>();
    // [7] SSD phase C
    chunk_inter_k<<<dim3(NCHKS, NH, BSZ), 256, C_SMEM>>>();
    // [8] out = y @ out_w^T + residual
    gemm_mma<true, false><<<dim3(1024 / BN, NROWS / BM), 256, GEMM_SMEM>>>(
        p_y, p_outw, (void*)out, x, NROWS, DM, DI);
}

// round 16
// speedup vs baseline: 1.1404x; 1.0079x over previous
#include <cuda_runtime.h>
#include <cuda_bf16.h>
#include <math.h>
#include <stdint.h>

// ---------------- problem constants ----------------------------------------
#define BSZ 2
#define TT 2048
#define DM 1024
#define DI 2048
#define NH 8
#define DS 64
#define DH 256
#define NROWS (BSZ*TT)          // 4096
#define EPSV 1e-6f
#define NCATP 1152              // B(512) | C(512) | dt(8) | pad -> 9*128
#define CHK 64
#define NCHKS (TT/CHK)          // 32

// ---------------- scratch (device globals) ---------------------------------
__device__ __nv_bfloat16 g_xn[(size_t)NROWS * DM];
__device__ __nv_bfloat16 g_xz[(size_t)NROWS * 2 * DI];
__device__ __nv_bfloat16 g_xs[(size_t)NROWS * DI];
__device__ __nv_bfloat16 g_bcdt[(size_t)NROWS * NCATP];
__device__ __nv_bfloat16 g_y [(size_t)NROWS * DI];
__device__ __nv_bfloat16 g_yi[(size_t)NROWS * DI];
__device__ float         g_hc [(size_t)16 * NCHKS * DS * DH];
__device__ __nv_bfloat16 g_hin[(size_t)16 * NCHKS * DS * DH];
__device__ float         g_S  [(size_t)16 * TT];
__device__ __nv_bfloat16 g_inw [(size_t)(2*DI) * DM];
__device__ __nv_bfloat16 g_wcat[(size_t)NCATP * DI];
__device__ __nv_bfloat16 g_outw[(size_t)DM * DI];

// ---------------- PTX helpers ----------------------------------------------
__device__ __forceinline__ uint32_t smem_u32(const void* p) {
    uint32_t a;
    asm("{ .reg .u64 t; cvta.to.shared.u64 t, %1; cvt.u32.u64 %0, t; }" : "=r"(a) : "l"(p));
    return a;
}

#define CP_ASYNC16(dst, src) \
    asm volatile("cp.async.cg.shared.global [%0], [%1], 16;" :: "r"(dst), "l"(src) : "memory")
#define CP_ASYNC4(dst, src) \
    asm volatile("cp.async.ca.shared.global [%0], [%1], 4;" :: "r"(dst), "l"(src) : "memory")
#define CP_COMMIT() asm volatile("cp.async.commit_group;" ::: "memory")
#define CP_WAIT1()  asm volatile("cp.async.wait_group 1;" ::: "memory")
#define CP_WAIT0()  asm volatile("cp.async.wait_group 0;" ::: "memory")

#define LDM_X4(r0, r1, r2, r3, addr) \
    asm volatile("ldmatrix.sync.aligned.m8n8.x4.shared.b16 {%0,%1,%2,%3}, [%4];" \
                 : "=r"(r0), "=r"(r1), "=r"(r2), "=r"(r3) : "r"(addr))
#define LDM_X4T(r0, r1, r2, r3, addr) \
    asm volatile("ldmatrix.sync.aligned.m8n8.x4.trans.shared.b16 {%0,%1,%2,%3}, [%4];" \
                 : "=r"(r0), "=r"(r1), "=r"(r2), "=r"(r3) : "r"(addr))
#define LDM_X2(r0, r1, addr) \
    asm volatile("ldmatrix.sync.aligned.m8n8.x2.shared.b16 {%0,%1}, [%2];" \
                 : "=r"(r0), "=r"(r1) : "r"(addr))

#define MMA16816(d, a0, a1, a2, a3, b0, b1) \
    asm volatile("mma.sync.aligned.m16n8k16.row.col.f32.bf16.bf16.f32 " \
                 "{%0,%1,%2,%3}, {%4,%5,%6,%7}, {%8,%9}, {%0,%1,%2,%3};" \
                 : "+f"((d)[0]), "+f"((d)[1]), "+f"((d)[2]), "+f"((d)[3]) \
                 : "r"(a0), "r"(a1), "r"(a2), "r"(a3), "r"(b0), "r"(b1))

// ---------------- bf16 mma.sync GEMM: C[M,N] = A[M,K] @ W[N,K]^T (+Res) ----
#define BM 128
#define BN 128
#define BK64 64
#define ROWB 144
#define SA_BYTES (BM * ROWB)
#define STG_BYTES (2 * SA_BYTES)
#define NST 3
#define GEMM_SMEM (NST * STG_BYTES)      // 110592

template <bool ADD_RES, bool OUT_BF16>
__global__ void __launch_bounds__(256)
gemm_mma(const __nv_bfloat16* __restrict__ A, const __nv_bfloat16* __restrict__ W,
         void* __restrict__ Cout, const float* __restrict__ Res,
         int M, int N, int K)
{
    extern __shared__ char sm[];
    uint32_t base = smem_u32(sm);

    int tid = threadIdx.x;
    int wid = tid >> 5, lane = tid & 31;
    int wm = wid >> 2, wn = wid & 3;
    int m0 = blockIdx.y * BM;
    int n0 = blockIdx.x * BN;

    const __nv_bfloat16* Ag = A + (size_t)m0 * K;
    const __nv_bfloat16* Wg = W + (size_t)n0 * K;

    float acc[4][4][4];
    #pragma unroll
    for (int i = 0; i < 4; i++)
        #pragma unroll
        for (int j = 0; j < 4; j++)
            #pragma unroll
            for (int f = 0; f < 4; f++) acc[i][j][f] = 0.f;

    int nk = K / BK64;

    auto load_stage = [&](int s, int k0) {
        uint32_t sA = base + s * STG_BYTES;
        uint32_t sB = sA + SA_BYTES;
        #pragma unroll
        for (int it = 0; it < 4; it++) {
            int i = tid + it * 256;
            int r = i >> 3, c = i & 7;
            CP_ASYNC16(sA + r * ROWB + c * 16, Ag + (size_t)r * K + k0 + c * 8);
        }
        #pragma unroll
        for (int it = 0; it < 4; it++) {
            int i = tid + it * 256;
            int r = i >> 3, c = i & 7;
            CP_ASYNC16(sB + r * ROWB + c * 16, Wg + (size_t)r * K + k0 + c * 8);
        }
    };

    load_stage(0, 0);      CP_COMMIT();
    load_stage(1, BK64);   CP_COMMIT();

    int stg = 0;
    for (int kt = 0; kt < nk; kt++) {
        CP_WAIT1();
        __syncthreads();

        int s2 = stg + 2; if (s2 >= NST) s2 -= NST;
        if (kt + 2 < nk) load_stage(s2, (kt + 2) * BK64);
        CP_COMMIT();

        uint32_t sA = base + stg * STG_BYTES;
        uint32_t sB = sA + SA_BYTES;

        #pragma unroll
        for (int ks = 0; ks < 4; ks++) {
            int colA = ks * 32 + (lane >> 4) * 16;
            int colB = ks * 32 + ((lane >> 3) & 1) * 16;
            uint32_t a[4][4], b[4][2];
            #pragma unroll
            for (int i = 0; i < 4; i++) {
                int row = wm * 64 + i * 16 + (lane & 15);
                LDM_X4(a[i][0], a[i][1], a[i][2], a[i][3],
                       sA + (uint32_t)(row * ROWB + colA));
            }
            #pragma unroll
            for (int j = 0; j < 4; j++) {
                int row = wn * 32 + j * 8 + (lane & 7);
                LDM_X2(b[j][0], b[j][1],
                       sB + (uint32_t)(row * ROWB + colB));
            }
            #pragma unroll
            for (int i = 0; i < 4; i++)
                #pragma unroll
                for (int j = 0; j < 4; j++)
                    MMA16816(acc[i][j], a[i][0], a[i][1], a[i][2], a[i][3],
                             b[j][0], b[j][1]);
        }
        stg++; if (stg >= NST) stg -= NST;
    }

    int gid = lane >> 2, t4 = lane & 3;
    #pragma unroll
    for (int i = 0; i < 4; i++) {
        int row0 = m0 + wm * 64 + i * 16 + gid;
        #pragma unroll
        for (int j = 0; j < 4; j++) {
            int col = n0 + wn * 32 + j * 8 + t4 * 2;
            size_t i0 = (size_t)row0 * N + col;
            size_t i1 = (size_t)(row0 + 8) * N + col;
            float2 v0 = make_float2(acc[i][j][0], acc[i][j][1]);
            float2 v1 = make_float2(acc[i][j][2], acc[i][j][3]);
            if (ADD_RES) {
                float2 r0 = *(const float2*)(Res + i0);
                float2 r1 = *(const float2*)(Res + i1);
                v0.x += r0.x; v0.y += r0.y;
                v1.x += r1.x; v1.y += r1.y;
            }
            if (OUT_BF16) {
                __nv_bfloat16* Cb = (__nv_bfloat16*)Cout;
                __nv_bfloat162 o0, o1;
                o0.x = __float2bfloat16(v0.x); o0.y = __float2bfloat16(v0.y);
                o1.x = __float2bfloat16(v1.x); o1.y = __float2bfloat16(v1.y);
                *(__nv_bfloat162*)(Cb + i0) = o0;
                *(__nv_bfloat162*)(Cb + i1) = o1;
            } else {
                float* Cf = (float*)Cout;
                *(float2*)(Cf + i0) = v0;
                *(float2*)(Cf + i1) = v1;
            }
        }
    }
}

// ---------------- all weight prep in one kernel -----------------------------
__global__ void prep_all_k(const float* __restrict__ in_w, const float* __restrict__ out_w,
                           const float* __restrict__ Bw, const float* __restrict__ Cw,
                           const float* __restrict__ dtw)
{
    const int N1 = 2 * DI * DM / 4;      // 2097152 (in_w)
    const int N2 = DM * DI / 4;          // 524288  (out_w)
    const int N3 = NCATP * DI / 4;       // 589824  (wcat)
    for (int idx = blockIdx.x * 256 + threadIdx.x; idx < N1 + N2 + N3; idx += gridDim.x * 256) {
        float4 v;
        __nv_bfloat162* dst;
        if (idx < N1) {
            v = ((const float4*)in_w)[idx];
            dst = (__nv_bfloat162*)g_inw + 2 * idx;
        } else if (idx < N1 + N2) {
            int i = idx - N1;
            v = ((const float4*)out_w)[i];
            dst = (__nv_bfloat162*)g_outw + 2 * i;
        } else {
            int i = idx - N1 - N2;
            int r = i >> 9;
            int kk = (i & 511) * 4;
            if (r < 512)       v = *(const float4*)(Bw + (size_t)r * DI + kk);
            else if (r < 1024) v = *(const float4*)(Cw + (size_t)(r - 512) * DI + kk);
            else if (r < 1032) v = *(const float4*)(dtw + (size_t)(r - 1024) * DI + kk);
            else               v = make_float4(0.f, 0.f, 0.f, 0.f);
            dst = (__nv_bfloat162*)g_wcat + 2 * i;
        }
        __nv_bfloat162 o0, o1;
        o0.x = __float2bfloat16(v.x); o0.y = __float2bfloat16(v.y);
        o1.x = __float2bfloat16(v.z); o1.y = __float2bfloat16(v.w);
        dst[0] = o0; dst[1] = o1;
    }
}

// ---------------- RMSNorm: one warp per row, no barriers --------------------
__global__ void __launch_bounds__(256)
rmsnorm_k(const float* __restrict__ x, const float* __restrict__ w)
{
    int row = blockIdx.x * 8 + (threadIdx.x >> 5);
    int lane = threadIdx.x & 31;
    const float4* xr = (const float4*)(x + (size_t)row * DM);
    const float4* wr = (const float4*)w;

    float4 v[8];
    float s = 0.f;
    #pragma unroll
    for (int k = 0; k < 8; k++) {
        v[k] = xr[lane + 32 * k];
        s += v[k].x * v[k].x + v[k].y * v[k].y + v[k].z * v[k].z + v[k].w * v[k].w;
    }
    #pragma unroll
    for (int o = 16; o; o >>= 1) s += __shfl_xor_sync(0xffffffffu, s, o);
    float sc = rsqrtf(s / (float)DM + EPSV);

    __nv_bfloat162* orow = (__nv_bfloat162*)(g_xn + (size_t)row * DM);
    #pragma unroll
    for (int k = 0; k < 8; k++) {
        float4 wv = wr[lane + 32 * k];
        __nv_bfloat162 o0, o1;
        o0.x = __float2bfloat16(v[k].x * sc * wv.x);
        o0.y = __float2bfloat16(v[k].y * sc * wv.y);
        o1.x = __float2bfloat16(v[k].z * sc * wv.z);
        o1.y = __float2bfloat16(v[k].w * sc * wv.w);
        orow[(lane + 32 * k) * 2]     = o0;
        orow[(lane + 32 * k) * 2 + 1] = o1;
    }
}

// ---------------- causal depthwise conv: 2 channels/thread, bf16x2 loads ----
__global__ void conv_silu_k(const float* __restrict__ cw, const float* __restrict__ cb)
{
    int cp = blockIdx.x * 256 + threadIdx.x;   // channel pair 0..1023
    int c = cp * 2;
    int t0 = blockIdx.y * 4;
    int b = blockIdx.z;
    float4 w0 = ((const float4*)cw)[c];
    float4 w1 = ((const float4*)cw)[c + 1];
    float2 bias = *(const float2*)(cb + c);
    size_t colbase = (size_t)b * TT * (2 * DI) + c;
    const size_t stride = 2 * DI;

    float2 xv[7];
    #pragma unroll
    for (int k = 0; k < 7; k++) {
        int t = t0 - 3 + k;
        if (t >= 0) {
            __nv_bfloat162 p = *(const __nv_bfloat162*)(g_xz + colbase + (size_t)t * stride);
            xv[k] = make_float2(__bfloat162float(p.x), __bfloat162float(p.y));
        } else xv[k] = make_float2(0.f, 0.f);
    }
    size_t obase = ((size_t)b * TT + t0) * DI + c;
    #pragma unroll
    for (int i = 0; i < 4; i++) {
        float a0 = bias.x + w0.x * xv[i].x + w0.y * xv[i + 1].x + w0.z * xv[i + 2].x + w0.w * xv[i + 3].x;
        float a1 = bias.y + w1.x * xv[i].y + w1.y * xv[i + 1].y + w1.z * xv[i + 2].y + w1.w * xv[i + 3].y;
        float s0 = a0 / (1.f + __expf(-a0));
        float s1 = a1 / (1.f + __expf(-a1));
        __nv_bfloat162 o;
        o.x = __float2bfloat16(s0);
        o.y = __float2bfloat16(s1);
        *(__nv_bfloat162*)(g_xs + obase + (size_t)i * DI) = o;
    }
}

// ---------------- SSD phase A: intra-chunk + state contributions ------------
#define AO_C 0
#define AO_B 9216
#define AO_P 18432
#define AO_W 27648
#define AO_X 36864
#define AO_S 70656
#define AO_DT 70912
#define AO_WJ 71168
#define A_SMEM 71424

__global__ void __launch_bounds__(256)
chunk_intra_k(const float* __restrict__ A_log, const float* __restrict__ dtb,
              const float* __restrict__ Dp)
{
    extern __shared__ char sm[];
    uint32_t base = smem_u32(sm);
    float* S  = (float*)(sm + AO_S);
    float* DT = (float*)(sm + AO_DT);
    float* WJ = (float*)(sm + AO_WJ);

    int tid = threadIdx.x;
    int wid = tid >> 5, lane = tid & 31;
    int wm = wid >> 2, wn = wid & 3;
    int chunk = blockIdx.x, h = blockIdx.y, b = blockIdx.z;
    int bh = b * NH + h;
    size_t rowbase = (size_t)b * TT + (size_t)chunk * CHK;

    const __nv_bfloat16* bsrc = g_bcdt + rowbase * NCATP + h * 64;
    for (int i = tid; i < 512; i += 256) {
        int r = i >> 3, c = i & 7;
        CP_ASYNC16(base + AO_B + r * 144 + c * 16, bsrc + (size_t)r * NCATP + c * 8);
        CP_ASYNC16(base + AO_C + r * 144 + c * 16, bsrc + (size_t)r * NCATP + 512 + c * 8);
    }
    for (int i = tid; i < 2048; i += 256) {
        int r = i >> 5, c = i & 31;
        CP_ASYNC16(base + AO_X + r * 528 + c * 16, g_xs + (rowbase + r) * DI + h * DH + c * 8);
    }
    CP_COMMIT();

    if (tid < 64) {
        float v = __bfloat162float(g_bcdt[(rowbase + tid) * NCATP + 1024 + h]) + dtb[h];
        DT[tid] = (v > 20.f) ? v : log1pf(expf(v));
    }
    CP_WAIT0();
    __syncthreads();

    float Ah = -__expf(A_log[h]);
    if (wid == 0) {
        float a0 = DT[lane] * Ah, a1 = DT[lane + 32] * Ah;
        #pragma unroll
        for (int off = 1; off < 32; off <<= 1) {
            float u0 = __shfl_up_sync(0xffffffffu, a0, off);
            float u1 = __shfl_up_sync(0xffffffffu, a1, off);
            if (lane >= off) { a0 += u0; a1 += u1; }
        }
        float tot = __shfl_sync(0xffffffffu, a0, 31);
        a1 += tot;
        S[lane] = a0; S[lane + 32] = a1;
    }
    __syncthreads();
    if (tid < 64) WJ[tid] = __expf(S[63] - S[tid]) * DT[tid];

    // GEMM1: G = C @ B^T
    float acc1[2][2][4];
    #pragma unroll
    for (int i = 0; i < 2; i++)
        #pragma unroll
        for (int j = 0; j < 2; j++)
            #pragma unroll
            for (int f = 0; f < 4; f++) acc1[i][j][f] = 0.f;

    #pragma unroll
    for (int ks = 0; ks < 4; ks++) {
        uint32_t a[2][4], bb[4];
        #pragma unroll
        for (int i = 0; i < 2; i++) {
            int row = wm * 32 + i * 16 + (lane & 15);
            LDM_X4(a[i][0], a[i][1], a[i][2], a[i][3],
                   base + AO_C + (uint32_t)(row * 144 + ks * 32 + (lane >> 4) * 16));
        }
        {
            int row = wn * 16 + (lane & 15);
            LDM_X4(bb[0], bb[1], bb[2], bb[3],
                   base + AO_B + (uint32_t)(row * 144 + ks * 32 + (lane >> 4) * 16));
        }
        #pragma unroll
        for (int i = 0; i < 2; i++) {
            MMA16816(acc1[i][0], a[i][0], a[i][1], a[i][2], a[i][3], bb[0], bb[2]);
            MMA16816(acc1[i][1], a[i][0], a[i][1], a[i][2], a[i][3], bb[1], bb[3]);
        }
    }

    int gid = lane >> 2, t4 = lane & 3;
    #pragma unroll
    for (int i = 0; i < 2; i++) {
        #pragma unroll
        for (int jd = 0; jd < 2; jd++) {
            int j0 = wn * 16 + jd * 8 + t4 * 2;
            #pragma unroll
            for (int hf = 0; hf < 2; hf++) {
                int t = wm * 32 + i * 16 + gid + hf * 8;
                float v0 = acc1[i][jd][hf * 2 + 0];
                float v1 = acc1[i][jd][hf * 2 + 1];
                float p0 = (t >= j0)     ? v0 * __expf(S[t] - S[j0])     * DT[j0]     : 0.f;
                float p1 = (t >= j0 + 1) ? v1 * __expf(S[t] - S[j0 + 1]) * DT[j0 + 1] : 0.f;
                __nv_bfloat162 pr;
                pr.x = __float2bfloat16(p0); pr.y = __float2bfloat16(p1);
                *(__nv_bfloat162*)(sm + AO_P + t * 144 + j0 * 2) = pr;
            }
        }
    }
    if (tid < 64) g_S[(size_t)bh * TT + chunk * CHK + tid] = S[tid];
    __syncthreads();

    for (int idx = tid; idx < 4096; idx += 256) {
        int j = idx >> 6, n = idx & 63;
        float bv = __bfloat162float(*(const __nv_bfloat16*)(sm + AO_B + j * 144 + n * 2));
        *(__nv_bfloat16*)(sm + AO_W + n * 144 + j * 2) = __float2bfloat16(bv * WJ[j]);
    }
    __syncthreads();

    float Dh = Dp[h];

    // GEMM2: Y_intra + D*x -> g_yi (bf16)
    {
        float acc[2][8][4];
        #pragma unroll
        for (int i = 0; i < 2; i++)
            #pragma unroll
            for (int j = 0; j < 8; j++)
                #pragma unroll
                for (int f = 0; f < 4; f++) acc[i][j][f] = 0.f;

        #pragma unroll
        for (int ks = 0; ks < 4; ks++) {
            uint32_t a[2][4];
            #pragma unroll
            for (int i = 0; i < 2; i++) {
                int row = wm * 32 + i * 16 + (lane & 15);
                LDM_X4(a[i][0], a[i][1], a[i][2], a[i][3],
                       base + AO_P + (uint32_t)(row * 144 + ks * 32 + (lane >> 4) * 16));
            }
            #pragma unroll
            for (int jj = 0; jj < 4; jj++) {
                int n0 = wn * 64 + jj * 16;
                int grp = lane >> 3, l8 = lane & 7;
                uint32_t addr = base + AO_X
                    + (uint32_t)(ks * 16 + (grp & 1) * 8 + l8) * 528
                    + (uint32_t)(n0 + (grp >> 1) * 8) * 2;
                uint32_t b0, b1, b2, b3;
                LDM_X4T(b0, b1, b2, b3, addr);
                #pragma unroll
                for (int i = 0; i < 2; i++) {
                    MMA16816(acc[i][jj * 2],     a[i][0], a[i][1], a[i][2], a[i][3], b0, b1);
                    MMA16816(acc[i][jj * 2 + 1], a[i][0], a[i][1], a[i][2], a[i][3], b2, b3);
                }
            }
        }
        #pragma unroll
        for (int i = 0; i < 2; i++)
            #pragma unroll
            for (int j8 = 0; j8 < 8; j8++)
                #pragma unroll
                for (int hf = 0; hf < 2; hf++) {
                    int t = wm * 32 + i * 16 + gid + hf * 8;
                    int d = wn * 64 + j8 * 8 + t4 * 2;
                    __nv_bfloat162 xv2 = *(const __nv_bfloat162*)(sm + AO_X + (uint32_t)(t * 528 + d * 2));
                    __nv_bfloat162 v;
                    v.x = __float2bfloat16(acc[i][j8][hf * 2]     + Dh * __bfloat162float(xv2.x));
                    v.y = __float2bfloat16(acc[i][j8][hf * 2 + 1] + Dh * __bfloat162float(xv2.y));
                    *(__nv_bfloat162*)(g_yi + (rowbase + t) * DI + h * DH + d) = v;
                }
    }

    // GEMM3: H_c = Wt @ X -> g_hc fp32
    {
        float acc[2][8][4];
        #pragma unroll
        for (int i = 0; i < 2; i++)
            #pragma unroll
            for (int j = 0; j < 8; j++)
                #pragma unroll
                for (int f = 0; f < 4; f++) acc[i][j][f] = 0.f;

        #pragma unroll
        for (int ks = 0; ks < 4; ks++) {
            uint32_t a[2][4];
            #pragma unroll
            for (int i = 0; i < 2; i++) {
                int row = wm * 32 + i * 16 + (lane & 15);
                LDM_X4(a[i][0], a[i][1], a[i][2], a[i][3],
                       base + AO_W + (uint32_t)(row * 144 + ks * 32 + (lane >> 4) * 16));
            }
            #pragma unroll
            for (int jj = 0; jj < 4; jj++) {
                int n0 = wn * 64 + jj * 16;
                int grp = lane >> 3, l8 = lane & 7;
                uint32_t addr = base + AO_X
                    + (uint32_t)(ks * 16 + (grp & 1) * 8 + l8) * 528
                    + (uint32_t)(n0 + (grp >> 1) * 8) * 2;
                uint32_t b0, b1, b2, b3;
                LDM_X4T(b0, b1, b2, b3, addr);
                #pragma unroll
                for (int i = 0; i < 2; i++) {
                    MMA16816(acc[i][jj * 2],     a[i][0], a[i][1], a[i][2], a[i][3], b0, b1);
                    MMA16816(acc[i][jj * 2 + 1], a[i][0], a[i][1], a[i][2], a[i][3], b2, b3);
                }
            }
        }
        #pragma unroll
        for (int i = 0; i < 2; i++)
            #pragma unroll
            for (int j8 = 0; j8 < 8; j8++)
                #pragma unroll
                for (int hf = 0; hf < 2; hf++) {
                    int n = wm * 32 + i * 16 + gid + hf * 8;
                    int d = wn * 64 + j8 * 8 + t4 * 2;
                    float2 v = make_float2(acc[i][j8][hf * 2], acc[i][j8][hf * 2 + 1]);
                    *(float2*)(g_hc + (((size_t)bh * NCHKS + chunk) * DS + n) * DH + d) = v;
                }
    }
}

// ---------------- SSD phase B: cross-chunk state recurrence (prefetched) ----
__global__ void __launch_bounds__(256)
state_scan_k()
{
    int dsl = blockIdx.x, h = blockIdx.y, b = blockIdx.z;
    int bh = b * NH + h;
    int tid = threadIdx.x;
    int n = tid >> 2;
    int dbase = dsl * 16 + (tid & 3) * 4;

    float4 hst = make_float4(0.f, 0.f, 0.f, 0.f);
    const size_t cstride = (size_t)DS * DH;
    size_t hb0 = ((size_t)bh * NCHKS * DS + n) * DH + dbase;

    float4 v = *(const float4*)(g_hc + hb0);
    for (int c = 0; c < NCHKS; c++) {
        float decay = __expf(g_S[(size_t)bh * TT + c * CHK + CHK - 1]);
        size_t hb = hb0 + (size_t)c * cstride;
        __nv_bfloat162 p0, p1;
        p0.x = __float2bfloat16(hst.x); p0.y = __float2bfloat16(hst.y);
        p1.x = __float2bfloat16(hst.z); p1.y = __float2bfloat16(hst.w);
        *(__nv_bfloat162*)(g_hin + hb) = p0;
        *(__nv_bfloat162*)(g_hin + hb + 2) = p1;

        float4 vn = make_float4(0.f, 0.f, 0.f, 0.f);
        if (c + 1 < NCHKS) vn = *(const float4*)(g_hc + hb + cstride);
        hst.x = decay * hst.x + v.x;
        hst.y = decay * hst.y + v.y;
        hst.z = decay * hst.z + v.z;
        hst.w = decay * hst.w + v.w;
        v = vn;
    }
}

// ---------------- SSD phase C: inter-chunk Y + combine + gate ---------------
#define CO_C 0
#define CO_H 9216
#define CO_S 43008
#define C_SMEM 43264

__global__ void __launch_bounds__(256)
chunk_inter_k()
{
    extern __shared__ char sm[];
    uint32_t base = smem_u32(sm);
    float* S = (float*)(sm + CO_S);

    int tid = threadIdx.x;
    int wid = tid >> 5, lane = tid & 31;
    int wm = wid >> 2, wn = wid & 3;
    int chunk = blockIdx.x, h = blockIdx.y, b = blockIdx.z;
    int bh = b * NH + h;
    size_t rowbase = (size_t)b * TT + (size_t)chunk * CHK;

    const __nv_bfloat16* csrc = g_bcdt + rowbase * NCATP + 512 + h * 64;
    for (int i = tid; i < 512; i += 256) {
        int r = i >> 3, c = i & 7;
        CP_ASYNC16(base + CO_C + r * 144 + c * 16, csrc + (size_t)r * NCATP + c * 8);
    }
    const __nv_bfloat16* hsrc = g_hin + ((size_t)bh * NCHKS + chunk) * DS * DH;
    for (int i = tid; i < 2048; i += 256) {
        int r = i >> 5, c = i & 31;
        CP_ASYNC16(base + CO_H + r * 528 + c * 16, hsrc + (size_t)r * DH + c * 8);
    }
    if (tid < 64)
        CP_ASYNC4(base + CO_S + tid * 4, g_S + (size_t)bh * TT + chunk * CHK + tid);
    CP_COMMIT();
    CP_WAIT0();
    __syncthreads();

    float acc[2][8][4];
    #pragma unroll
    for (int i = 0; i < 2; i++)
        #pragma unroll
        for (int j = 0; j < 8; j++)
            #pragma unroll
            for (int f = 0; f < 4; f++) acc[i][j][f] = 0.f;

    #pragma unroll
    for (int ks = 0; ks < 4; ks++) {
        uint32_t a[2][4];
        #pragma unroll
        for (int i = 0; i < 2; i++) {
            int row = wm * 32 + i * 16 + (lane & 15);
            LDM_X4(a[i][0], a[i][1], a[i][2], a[i][3],
                   base + CO_C + (uint32_t)(row * 144 + ks * 32 + (lane >> 4) * 16));
        }
        #pragma unroll
        for (int jj = 0; jj < 4; jj++) {
            int n0 = wn * 64 + jj * 16;
            int grp = lane >> 3, l8 = lane & 7;
            uint32_t addr = base + CO_H
                + (uint32_t)(ks * 16 + (grp & 1) * 8 + l8) * 528
                + (uint32_t)(n0 + (grp >> 1) * 8) * 2;
            uint32_t b0, b1, b2, b3;
            LDM_X4T(b0, b1, b2, b3, addr);
            #pragma unroll
            for (int i = 0; i < 2; i++) {
                MMA16816(acc[i][jj * 2],     a[i][0], a[i][1], a[i][2], a[i][3], b0, b1);
                MMA16816(acc[i][jj * 2 + 1], a[i][0], a[i][1], a[i][2], a[i][3], b2, b3);
            }
        }
    }

    int gid = lane >> 2, t4 = lane & 3;
    #pragma unroll
    for (int i = 0; i < 2; i++)
        #pragma unroll
        for (int j8 = 0; j8 < 8; j8++)
            #pragma unroll
            for (int hf = 0; hf < 2; hf++) {
                int t = wm * 32 + i * 16 + gid + hf * 8;
                int d = wn * 64 + j8 * 8 + t4 * 2;
                float et = __expf(S[t]);
                size_t gi = (rowbase + t) * DI + h * DH + d;
                __nv_bfloat162 yi = *(const __nv_bfloat162*)(g_yi + gi);
                __nv_bfloat162 z2 = *(const __nv_bfloat162*)(g_xz + (rowbase + t) * (2 * DI) + DI + h * DH + d);
                float z0 = __bfloat162float(z2.x), z1 = __bfloat162float(z2.y);
                float y0 = acc[i][j8][hf * 2 + 0] * et + __bfloat162float(yi.x);
                float y1 = acc[i][j8][hf * 2 + 1] * et + __bfloat162float(yi.y);
                float s0 = z0 / (1.f + __expf(-z0));
                float s1 = z1 / (1.f + __expf(-z1));
                __nv_bfloat162 o;
                o.x = __float2bfloat16(y0 * s0);
                o.y = __float2bfloat16(y1 * s1);
                *(__nv_bfloat162*)(g_y + gi) = o;
            }
}

// ---------------- launch ----------------------------------------------------
extern "C" void kernel_launch(void* const* d_in, const int* in_sizes, int n_in,
                              void* d_out, int out_size)
{
    const float* x      = (const float*)d_in[0];
    const float* norm_w = (const float*)d_in[1];
    const float* in_w   = (const float*)d_in[2];
    const float* conv_w = (const float*)d_in[3];
    const float* conv_b = (const float*)d_in[4];
    const float* A_log  = (const float*)d_in[5];
    const float* B_w    = (const float*)d_in[6];
    const float* C_w    = (const float*)d_in[7];
    const float* dt_w   = (const float*)d_in[8];
    const float* dt_b   = (const float*)d_in[9];
    const float* Dp     = (const float*)d_in[10];
    const float* out_w  = (const float*)d_in[11];
    float* out = (float*)d_out;

    __nv_bfloat16 *p_xn, *p_xs, *p_y, *p_inw, *p_wcat, *p_outw, *p_bcdt, *p_xz;
    cudaGetSymbolAddress((void**)&p_xn, g_xn);
    cudaGetSymbolAddress((void**)&p_xz, g_xz);
    cudaGetSymbolAddress((void**)&p_xs, g_xs);
    cudaGetSymbolAddress((void**)&p_bcdt, g_bcdt);
    cudaGetSymbolAddress((void**)&p_y, g_y);
    cudaGetSymbolAddress((void**)&p_inw, g_inw);
    cudaGetSymbolAddress((void**)&p_wcat, g_wcat);
    cudaGetSymbolAddress((void**)&p_outw, g_outw);

    cudaFuncSetAttribute(gemm_mma<false, true>,  cudaFuncAttributeMaxDynamicSharedMemorySize, GEMM_SMEM);
    cudaFuncSetAttribute(gemm_mma<true, false>,  cudaFuncAttributeMaxDynamicSharedMemorySize, GEMM_SMEM);
    cudaFuncSetAttribute(chunk_intra_k, cudaFuncAttributeMaxDynamicSharedMemorySize, A_SMEM);
    cudaFuncSetAttribute(chunk_inter_k, cudaFuncAttributeMaxDynamicSharedMemorySize, C_SMEM);

    // [0] all weights -> bf16
    prep_all_k<<<512, 256>>>(in_w, out_w, B_w, C_w, dt_w);
    // [1] RMSNorm -> bf16 (warp-per-row)
    rmsnorm_k<<<NROWS / 8, 256>>>(x, norm_w);
    // [2] xz = xn @ in_w^T -> bf16
    gemm_mma<false, true><<<dim3(4096 / BN, NROWS / BM), 256, GEMM_SMEM>>>(
        p_xn, p_inw, (void*)p_xz, nullptr, NROWS, 2 * DI, DM);
    // [3] causal conv + SiLU -> bf16 (2 ch/thread, ncu capture slot)
    conv_silu_k<<<dim3(DI / 512, TT / 4, BSZ), 256>>>(conv_w, conv_b);
    // [4] [B | C | dt] = xs @ wcat^T -> bf16
    gemm_mma<false, true><<<dim3(NCATP / BN, NROWS / BM), 256, GEMM_SMEM>>>(
        p_xs, p_wcat, (void*)p_bcdt, nullptr, NROWS, NCATP, DI);
    // [5] SSD phase A (+ D*x fused)
    chunk_intra_k<<<dim3(NCHKS, NH, BSZ), 256, A_SMEM>>>(A_log, dt_b, Dp);
    // [6] SSD phase B
    state_scan_k<<<dim3(16, NH, BSZ), 256>>>();
    // [7] SSD phase C
    chunk_inter_k<<<dim3(NCHKS, NH, BSZ), 256, C_SMEM>>>();
    // [8] out = y @ out_w^T + residual
    gemm_mma<true, false><<<dim3(1024 / BN, NROWS / BM), 256, GEMM_SMEM>>>(
        p_y, p_outw, (void*)out, x, NROWS, DM, DI);
}

// round 17
// speedup vs baseline: 1.1525x; 1.0106x over previous
#include <cuda_runtime.h>
#include <cuda_bf16.h>
#include <math.h>
#include <stdint.h>

// ---------------- problem constants ----------------------------------------
#define BSZ 2
#define TT 2048
#define DM 1024
#define DI 2048
#define NH 8
#define DS 64
#define DH 256
#define NROWS (BSZ*TT)          // 4096
#define EPSV 1e-6f
#define NCATP 1152              // B(512) | C(512) | dt(8) | pad -> 9*128
#define CHK 64
#define NCHKS (TT/CHK)          // 32

// ---------------- scratch (device globals) ---------------------------------
__device__ __nv_bfloat16 g_xn[(size_t)NROWS * DM];
__device__ __nv_bfloat16 g_xz[(size_t)NROWS * 2 * DI];
__device__ __nv_bfloat16 g_xs[(size_t)NROWS * DI];
__device__ __nv_bfloat16 g_bcdt[(size_t)NROWS * NCATP];
__device__ __nv_bfloat16 g_y [(size_t)NROWS * DI];
__device__ __nv_bfloat16 g_yi[(size_t)NROWS * DI];
__device__ float         g_hc [(size_t)16 * NCHKS * DS * DH];
__device__ __nv_bfloat16 g_hin[(size_t)16 * NCHKS * DS * DH];
__device__ float         g_S  [(size_t)16 * TT];
__device__ __nv_bfloat16 g_inw [(size_t)(2*DI) * DM];
__device__ __nv_bfloat16 g_wcat[(size_t)NCATP * DI];
__device__ __nv_bfloat16 g_outw[(size_t)DM * DI];

// ---------------- PTX helpers ----------------------------------------------
__device__ __forceinline__ uint32_t smem_u32(const void* p) {
    uint32_t a;
    asm("{ .reg .u64 t; cvta.to.shared.u64 t, %1; cvt.u32.u64 %0, t; }" : "=r"(a) : "l"(p));
    return a;
}

#define CP_ASYNC16(dst, src) \
    asm volatile("cp.async.cg.shared.global [%0], [%1], 16;" :: "r"(dst), "l"(src) : "memory")
#define CP_ASYNC4(dst, src) \
    asm volatile("cp.async.ca.shared.global [%0], [%1], 4;" :: "r"(dst), "l"(src) : "memory")
#define CP_COMMIT() asm volatile("cp.async.commit_group;" ::: "memory")
#define CP_WAIT1()  asm volatile("cp.async.wait_group 1;" ::: "memory")
#define CP_WAIT0()  asm volatile("cp.async.wait_group 0;" ::: "memory")

#define LDM_X4(r0, r1, r2, r3, addr) \
    asm volatile("ldmatrix.sync.aligned.m8n8.x4.shared.b16 {%0,%1,%2,%3}, [%4];" \
                 : "=r"(r0), "=r"(r1), "=r"(r2), "=r"(r3) : "r"(addr))
#define LDM_X4T(r0, r1, r2, r3, addr) \
    asm volatile("ldmatrix.sync.aligned.m8n8.x4.trans.shared.b16 {%0,%1,%2,%3}, [%4];" \
                 : "=r"(r0), "=r"(r1), "=r"(r2), "=r"(r3) : "r"(addr))
#define LDM_X2(r0, r1, addr) \
    asm volatile("ldmatrix.sync.aligned.m8n8.x2.shared.b16 {%0,%1}, [%2];" \
                 : "=r"(r0), "=r"(r1) : "r"(addr))

#define MMA16816(d, a0, a1, a2, a3, b0, b1) \
    asm volatile("mma.sync.aligned.m16n8k16.row.col.f32.bf16.bf16.f32 " \
                 "{%0,%1,%2,%3}, {%4,%5,%6,%7}, {%8,%9}, {%0,%1,%2,%3};" \
                 : "+f"((d)[0]), "+f"((d)[1]), "+f"((d)[2]), "+f"((d)[3]) \
                 : "r"(a0), "r"(a1), "r"(a2), "r"(a3), "r"(b0), "r"(b1))

// ---------------- bf16 mma.sync GEMM: C[M,N] = A[M,K] @ W[N,K]^T (+Res) ----
#define BM 128
#define BN 128
#define BK64 64
#define ROWB 144
#define SA_BYTES (BM * ROWB)
#define STG_BYTES (2 * SA_BYTES)
#define NST 3
#define GEMM_SMEM (NST * STG_BYTES)      // 110592

template <bool ADD_RES, bool OUT_BF16>
__global__ void __launch_bounds__(256)
gemm_mma(const __nv_bfloat16* __restrict__ A, const __nv_bfloat16* __restrict__ W,
         void* __restrict__ Cout, const float* __restrict__ Res,
         int M, int N, int K)
{
    extern __shared__ char sm[];
    uint32_t base = smem_u32(sm);

    int tid = threadIdx.x;
    int wid = tid >> 5, lane = tid & 31;
    int wm = wid >> 2, wn = wid & 3;
    int m0 = blockIdx.y * BM;
    int n0 = blockIdx.x * BN;

    const __nv_bfloat16* Ag = A + (size_t)m0 * K;
    const __nv_bfloat16* Wg = W + (size_t)n0 * K;

    float acc[4][4][4];
    #pragma unroll
    for (int i = 0; i < 4; i++)
        #pragma unroll
        for (int j = 0; j < 4; j++)
            #pragma unroll
            for (int f = 0; f < 4; f++) acc[i][j][f] = 0.f;

    int nk = K / BK64;

    auto load_stage = [&](int s, int k0) {
        uint32_t sA = base + s * STG_BYTES;
        uint32_t sB = sA + SA_BYTES;
        #pragma unroll
        for (int it = 0; it < 4; it++) {
            int i = tid + it * 256;
            int r = i >> 3, c = i & 7;
            CP_ASYNC16(sA + r * ROWB + c * 16, Ag + (size_t)r * K + k0 + c * 8);
        }
        #pragma unroll
        for (int it = 0; it < 4; it++) {
            int i = tid + it * 256;
            int r = i >> 3, c = i & 7;
            CP_ASYNC16(sB + r * ROWB + c * 16, Wg + (size_t)r * K + k0 + c * 8);
        }
    };

    load_stage(0, 0);      CP_COMMIT();
    load_stage(1, BK64);   CP_COMMIT();

    int stg = 0;
    for (int kt = 0; kt < nk; kt++) {
        CP_WAIT1();
        __syncthreads();

        int s2 = stg + 2; if (s2 >= NST) s2 -= NST;
        if (kt + 2 < nk) load_stage(s2, (kt + 2) * BK64);
        CP_COMMIT();

        uint32_t sA = base + stg * STG_BYTES;
        uint32_t sB = sA + SA_BYTES;

        #pragma unroll
        for (int ks = 0; ks < 4; ks++) {
            int colA = ks * 32 + (lane >> 4) * 16;
            int colB = ks * 32 + ((lane >> 3) & 1) * 16;
            uint32_t a[4][4], b[4][2];
            #pragma unroll
            for (int i = 0; i < 4; i++) {
                int row = wm * 64 + i * 16 + (lane & 15);
                LDM_X4(a[i][0], a[i][1], a[i][2], a[i][3],
                       sA + (uint32_t)(row * ROWB + colA));
            }
            #pragma unroll
            for (int j = 0; j < 4; j++) {
                int row = wn * 32 + j * 8 + (lane & 7);
                LDM_X2(b[j][0], b[j][1],
                       sB + (uint32_t)(row * ROWB + colB));
            }
            #pragma unroll
            for (int i = 0; i < 4; i++)
                #pragma unroll
                for (int j = 0; j < 4; j++)
                    MMA16816(acc[i][j], a[i][0], a[i][1], a[i][2], a[i][3],
                             b[j][0], b[j][1]);
        }
        stg++; if (stg >= NST) stg -= NST;
    }

    int gid = lane >> 2, t4 = lane & 3;
    #pragma unroll
    for (int i = 0; i < 4; i++) {
        int row0 = m0 + wm * 64 + i * 16 + gid;
        #pragma unroll
        for (int j = 0; j < 4; j++) {
            int col = n0 + wn * 32 + j * 8 + t4 * 2;
            size_t i0 = (size_t)row0 * N + col;
            size_t i1 = (size_t)(row0 + 8) * N + col;
            float2 v0 = make_float2(acc[i][j][0], acc[i][j][1]);
            float2 v1 = make_float2(acc[i][j][2], acc[i][j][3]);
            if (ADD_RES) {
                float2 r0 = *(const float2*)(Res + i0);
                float2 r1 = *(const float2*)(Res + i1);
                v0.x += r0.x; v0.y += r0.y;
                v1.x += r1.x; v1.y += r1.y;
            }
            if (OUT_BF16) {
                __nv_bfloat16* Cb = (__nv_bfloat16*)Cout;
                __nv_bfloat162 o0, o1;
                o0.x = __float2bfloat16(v0.x); o0.y = __float2bfloat16(v0.y);
                o1.x = __float2bfloat16(v1.x); o1.y = __float2bfloat16(v1.y);
                *(__nv_bfloat162*)(Cb + i0) = o0;
                *(__nv_bfloat162*)(Cb + i1) = o1;
            } else {
                float* Cf = (float*)Cout;
                *(float2*)(Cf + i0) = v0;
                *(float2*)(Cf + i1) = v1;
            }
        }
    }
}

// ---------------- weight prep: in_w (needed by gemm1) -----------------------
__global__ void prep_inw_k(const float* __restrict__ in_w)
{
    const int N1 = 2 * DI * DM / 4;
    for (int i = blockIdx.x * 256 + threadIdx.x; i < N1; i += gridDim.x * 256) {
        float4 v = ((const float4*)in_w)[i];
        __nv_bfloat162 o0, o1;
        o0.x = __float2bfloat16(v.x); o0.y = __float2bfloat16(v.y);
        o1.x = __float2bfloat16(v.z); o1.y = __float2bfloat16(v.w);
        ((__nv_bfloat162*)g_inw)[2 * i] = o0;
        ((__nv_bfloat162*)g_inw)[2 * i + 1] = o1;
    }
}

// ---------------- weight prep: out_w + wcat (side stream) -------------------
__global__ void prep_rest_k(const float* __restrict__ out_w, const float* __restrict__ Bw,
                            const float* __restrict__ Cw, const float* __restrict__ dtw)
{
    const int N2 = DM * DI / 4;
    const int N3 = NCATP * DI / 4;
    for (int idx = blockIdx.x * 256 + threadIdx.x; idx < N2 + N3; idx += gridDim.x * 256) {
        float4 v;
        __nv_bfloat162* dst;
        if (idx < N2) {
            v = ((const float4*)out_w)[idx];
            dst = (__nv_bfloat162*)g_outw + 2 * idx;
        } else {
            int i = idx - N2;
            int r = i >> 9;
            int kk = (i & 511) * 4;
            if (r < 512)       v = *(const float4*)(Bw + (size_t)r * DI + kk);
            else if (r < 1024) v = *(const float4*)(Cw + (size_t)(r - 512) * DI + kk);
            else if (r < 1032) v = *(const float4*)(dtw + (size_t)(r - 1024) * DI + kk);
            else               v = make_float4(0.f, 0.f, 0.f, 0.f);
            dst = (__nv_bfloat162*)g_wcat + 2 * i;
        }
        __nv_bfloat162 o0, o1;
        o0.x = __float2bfloat16(v.x); o0.y = __float2bfloat16(v.y);
        o1.x = __float2bfloat16(v.z); o1.y = __float2bfloat16(v.w);
        dst[0] = o0; dst[1] = o1;
    }
}

// ---------------- RMSNorm: one warp per row, no barriers --------------------
__global__ void __launch_bounds__(256)
rmsnorm_k(const float* __restrict__ x, const float* __restrict__ w)
{
    int row = blockIdx.x * 8 + (threadIdx.x >> 5);
    int lane = threadIdx.x & 31;
    const float4* xr = (const float4*)(x + (size_t)row * DM);
    const float4* wr = (const float4*)w;

    float4 v[8];
    float s = 0.f;
    #pragma unroll
    for (int k = 0; k < 8; k++) {
        v[k] = xr[lane + 32 * k];
        s += v[k].x * v[k].x + v[k].y * v[k].y + v[k].z * v[k].z + v[k].w * v[k].w;
    }
    #pragma unroll
    for (int o = 16; o; o >>= 1) s += __shfl_xor_sync(0xffffffffu, s, o);
    float sc = rsqrtf(s / (float)DM + EPSV);

    __nv_bfloat162* orow = (__nv_bfloat162*)(g_xn + (size_t)row * DM);
    #pragma unroll
    for (int k = 0; k < 8; k++) {
        float4 wv = wr[lane + 32 * k];
        __nv_bfloat162 o0, o1;
        o0.x = __float2bfloat16(v[k].x * sc * wv.x);
        o0.y = __float2bfloat16(v[k].y * sc * wv.y);
        o1.x = __float2bfloat16(v[k].z * sc * wv.z);
        o1.y = __float2bfloat16(v[k].w * sc * wv.w);
        orow[(lane + 32 * k) * 2]     = o0;
        orow[(lane + 32 * k) * 2 + 1] = o1;
    }
}

// ---------------- causal depthwise conv: 2 ch x 8 t per thread --------------
__global__ void conv_silu_k(const float* __restrict__ cw, const float* __restrict__ cb)
{
    int cp = blockIdx.x * 256 + threadIdx.x;   // channel pair 0..1023
    int c = cp * 2;
    int t0 = blockIdx.y * 8;
    int b = blockIdx.z;
    float4 w0 = ((const float4*)cw)[c];
    float4 w1 = ((const float4*)cw)[c + 1];
    float2 bias = *(const float2*)(cb + c);
    size_t colbase = (size_t)b * TT * (2 * DI) + c;
    const size_t stride = 2 * DI;

    float2 xv[11];
    #pragma unroll
    for (int k = 0; k < 11; k++) {
        int t = t0 - 3 + k;
        if (t >= 0) {
            __nv_bfloat162 p = *(const __nv_bfloat162*)(g_xz + colbase + (size_t)t * stride);
            xv[k] = make_float2(__bfloat162float(p.x), __bfloat162float(p.y));
        } else xv[k] = make_float2(0.f, 0.f);
    }
    size_t obase = ((size_t)b * TT + t0) * DI + c;
    #pragma unroll
    for (int i = 0; i < 8; i++) {
        float a0 = bias.x + w0.x * xv[i].x + w0.y * xv[i + 1].x + w0.z * xv[i + 2].x + w0.w * xv[i + 3].x;
        float a1 = bias.y + w1.x * xv[i].y + w1.y * xv[i + 1].y + w1.z * xv[i + 2].y + w1.w * xv[i + 3].y;
        float s0 = a0 / (1.f + __expf(-a0));
        float s1 = a1 / (1.f + __expf(-a1));
        __nv_bfloat162 o;
        o.x = __float2bfloat16(s0);
        o.y = __float2bfloat16(s1);
        *(__nv_bfloat162*)(g_xs + obase + (size_t)i * DI) = o;
    }
}

// ---------------- SSD phase A: intra-chunk + state contributions ------------
#define AO_C 0
#define AO_B 9216
#define AO_P 18432
#define AO_W 27648
#define AO_X 36864
#define AO_S 70656
#define AO_DT 70912
#define AO_WJ 71168
#define A_SMEM 71424

__global__ void __launch_bounds__(256)
chunk_intra_k(const float* __restrict__ A_log, const float* __restrict__ dtb,
              const float* __restrict__ Dp)
{
    extern __shared__ char sm[];
    uint32_t base = smem_u32(sm);
    float* S  = (float*)(sm + AO_S);
    float* DT = (float*)(sm + AO_DT);
    float* WJ = (float*)(sm + AO_WJ);

    int tid = threadIdx.x;
    int wid = tid >> 5, lane = tid & 31;
    int wm = wid >> 2, wn = wid & 3;
    int chunk = blockIdx.x, h = blockIdx.y, b = blockIdx.z;
    int bh = b * NH + h;
    size_t rowbase = (size_t)b * TT + (size_t)chunk * CHK;

    const __nv_bfloat16* bsrc = g_bcdt + rowbase * NCATP + h * 64;
    for (int i = tid; i < 512; i += 256) {
        int r = i >> 3, c = i & 7;
        CP_ASYNC16(base + AO_B + r * 144 + c * 16, bsrc + (size_t)r * NCATP + c * 8);
        CP_ASYNC16(base + AO_C + r * 144 + c * 16, bsrc + (size_t)r * NCATP + 512 + c * 8);
    }
    for (int i = tid; i < 2048; i += 256) {
        int r = i >> 5, c = i & 31;
        CP_ASYNC16(base + AO_X + r * 528 + c * 16, g_xs + (rowbase + r) * DI + h * DH + c * 8);
    }
    CP_COMMIT();

    if (tid < 64) {
        float v = __bfloat162float(g_bcdt[(rowbase + tid) * NCATP + 1024 + h]) + dtb[h];
        DT[tid] = (v > 20.f) ? v : log1pf(expf(v));
    }
    CP_WAIT0();
    __syncthreads();

    float Ah = -__expf(A_log[h]);
    if (wid == 0) {
        float a0 = DT[lane] * Ah, a1 = DT[lane + 32] * Ah;
        #pragma unroll
        for (int off = 1; off < 32; off <<= 1) {
            float u0 = __shfl_up_sync(0xffffffffu, a0, off);
            float u1 = __shfl_up_sync(0xffffffffu, a1, off);
            if (lane >= off) { a0 += u0; a1 += u1; }
        }
        float tot = __shfl_sync(0xffffffffu, a0, 31);
        a1 += tot;
        S[lane] = a0; S[lane + 32] = a1;
    }
    __syncthreads();
    if (tid < 64) WJ[tid] = __expf(S[63] - S[tid]) * DT[tid];

    // GEMM1: G = C @ B^T
    float acc1[2][2][4];
    #pragma unroll
    for (int i = 0; i < 2; i++)
        #pragma unroll
        for (int j = 0; j < 2; j++)
            #pragma unroll
            for (int f = 0; f < 4; f++) acc1[i][j][f] = 0.f;

    #pragma unroll
    for (int ks = 0; ks < 4; ks++) {
        uint32_t a[2][4], bb[4];
        #pragma unroll
        for (int i = 0; i < 2; i++) {
            int row = wm * 32 + i * 16 + (lane & 15);
            LDM_X4(a[i][0], a[i][1], a[i][2], a[i][3],
                   base + AO_C + (uint32_t)(row * 144 + ks * 32 + (lane >> 4) * 16));
        }
        {
            int row = wn * 16 + (lane & 15);
            LDM_X4(bb[0], bb[1], bb[2], bb[3],
                   base + AO_B + (uint32_t)(row * 144 + ks * 32 + (lane >> 4) * 16));
        }
        #pragma unroll
        for (int i = 0; i < 2; i++) {
            MMA16816(acc1[i][0], a[i][0], a[i][1], a[i][2], a[i][3], bb[0], bb[2]);
            MMA16816(acc1[i][1], a[i][0], a[i][1], a[i][2], a[i][3], bb[1], bb[3]);
        }
    }

    int gid = lane >> 2, t4 = lane & 3;
    #pragma unroll
    for (int i = 0; i < 2; i++) {
        #pragma unroll
        for (int jd = 0; jd < 2; jd++) {
            int j0 = wn * 16 + jd * 8 + t4 * 2;
            #pragma unroll
            for (int hf = 0; hf < 2; hf++) {
                int t = wm * 32 + i * 16 + gid + hf * 8;
                float v0 = acc1[i][jd][hf * 2 + 0];
                float v1 = acc1[i][jd][hf * 2 + 1];
                float p0 = (t >= j0)     ? v0 * __expf(S[t] - S[j0])     * DT[j0]     : 0.f;
                float p1 = (t >= j0 + 1) ? v1 * __expf(S[t] - S[j0 + 1]) * DT[j0 + 1] : 0.f;
                __nv_bfloat162 pr;
                pr.x = __float2bfloat16(p0); pr.y = __float2bfloat16(p1);
                *(__nv_bfloat162*)(sm + AO_P + t * 144 + j0 * 2) = pr;
            }
        }
    }
    if (tid < 64) g_S[(size_t)bh * TT + chunk * CHK + tid] = S[tid];
    __syncthreads();

    for (int idx = tid; idx < 4096; idx += 256) {
        int j = idx >> 6, n = idx & 63;
        float bv = __bfloat162float(*(const __nv_bfloat16*)(sm + AO_B + j * 144 + n * 2));
        *(__nv_bfloat16*)(sm + AO_W + n * 144 + j * 2) = __float2bfloat16(bv * WJ[j]);
    }
    __syncthreads();

    float Dh = Dp[h];

    // GEMM2: Y_intra + D*x -> g_yi (bf16)
    {
        float acc[2][8][4];
        #pragma unroll
        for (int i = 0; i < 2; i++)
            #pragma unroll
            for (int j = 0; j < 8; j++)
                #pragma unroll
                for (int f = 0; f < 4; f++) acc[i][j][f] = 0.f;

        #pragma unroll
        for (int ks = 0; ks < 4; ks++) {
            uint32_t a[2][4];
            #pragma unroll
            for (int i = 0; i < 2; i++) {
                int row = wm * 32 + i * 16 + (lane & 15);
                LDM_X4(a[i][0], a[i][1], a[i][2], a[i][3],
                       base + AO_P + (uint32_t)(row * 144 + ks * 32 + (lane >> 4) * 16));
            }
            #pragma unroll
            for (int jj = 0; jj < 4; jj++) {
                int n0 = wn * 64 + jj * 16;
                int grp = lane >> 3, l8 = lane & 7;
                uint32_t addr = base + AO_X
                    + (uint32_t)(ks * 16 + (grp & 1) * 8 + l8) * 528
                    + (uint32_t)(n0 + (grp >> 1) * 8) * 2;
                uint32_t b0, b1, b2, b3;
                LDM_X4T(b0, b1, b2, b3, addr);
                #pragma unroll
                for (int i = 0; i < 2; i++) {
                    MMA16816(acc[i][jj * 2],     a[i][0], a[i][1], a[i][2], a[i][3], b0, b1);
                    MMA16816(acc[i][jj * 2 + 1], a[i][0], a[i][1], a[i][2], a[i][3], b2, b3);
                }
            }
        }
        #pragma unroll
        for (int i = 0; i < 2; i++)
            #pragma unroll
            for (int j8 = 0; j8 < 8; j8++)
                #pragma unroll
                for (int hf = 0; hf < 2; hf++) {
                    int t = wm * 32 + i * 16 + gid + hf * 8;
                    int d = wn * 64 + j8 * 8 + t4 * 2;
                    __nv_bfloat162 xv2 = *(const __nv_bfloat162*)(sm + AO_X + (uint32_t)(t * 528 + d * 2));
                    __nv_bfloat162 v;
                    v.x = __float2bfloat16(acc[i][j8][hf * 2]     + Dh * __bfloat162float(xv2.x));
                    v.y = __float2bfloat16(acc[i][j8][hf * 2 + 1] + Dh * __bfloat162float(xv2.y));
                    *(__nv_bfloat162*)(g_yi + (rowbase + t) * DI + h * DH + d) = v;
                }
    }

    // GEMM3: H_c = Wt @ X -> g_hc fp32
    {
        float acc[2][8][4];
        #pragma unroll
        for (int i = 0; i < 2; i++)
            #pragma unroll
            for (int j = 0; j < 8; j++)
                #pragma unroll
                for (int f = 0; f < 4; f++) acc[i][j][f] = 0.f;

        #pragma unroll
        for (int ks = 0; ks < 4; ks++) {
            uint32_t a[2][4];
            #pragma unroll
            for (int i = 0; i < 2; i++) {
                int row = wm * 32 + i * 16 + (lane & 15);
                LDM_X4(a[i][0], a[i][1], a[i][2], a[i][3],
                       base + AO_W + (uint32_t)(row * 144 + ks * 32 + (lane >> 4) * 16));
            }
            #pragma unroll
            for (int jj = 0; jj < 4; jj++) {
                int n0 = wn * 64 + jj * 16;
                int grp = lane >> 3, l8 = lane & 7;
                uint32_t addr = base + AO_X
                    + (uint32_t)(ks * 16 + (grp & 1) * 8 + l8) * 528
                    + (uint32_t)(n0 + (grp >> 1) * 8) * 2;
                uint32_t b0, b1, b2, b3;
                LDM_X4T(b0, b1, b2, b3, addr);
                #pragma unroll
                for (int i = 0; i < 2; i++) {
                    MMA16816(acc[i][jj * 2],     a[i][0], a[i][1], a[i][2], a[i][3], b0, b1);
                    MMA16816(acc[i][jj * 2 + 1], a[i][0], a[i][1], a[i][2], a[i][3], b2, b3);
                }
            }
        }
        #pragma unroll
        for (int i = 0; i < 2; i++)
            #pragma unroll
            for (int j8 = 0; j8 < 8; j8++)
                #pragma unroll
                for (int hf = 0; hf < 2; hf++) {
                    int n = wm * 32 + i * 16 + gid + hf * 8;
                    int d = wn * 64 + j8 * 8 + t4 * 2;
                    float2 v = make_float2(acc[i][j8][hf * 2], acc[i][j8][hf * 2 + 1]);
                    *(float2*)(g_hc + (((size_t)bh * NCHKS + chunk) * DS + n) * DH + d) = v;
                }
    }
}

// ---------------- SSD phase B: cross-chunk state recurrence (prefetched) ----
__global__ void __launch_bounds__(256)
state_scan_k()
{
    int dsl = blockIdx.x, h = blockIdx.y, b = blockIdx.z;
    int bh = b * NH + h;
    int tid = threadIdx.x;
    int n = tid >> 2;
    int dbase = dsl * 16 + (tid & 3) * 4;

    float4 hst = make_float4(0.f, 0.f, 0.f, 0.f);
    const size_t cstride = (size_t)DS * DH;
    size_t hb0 = ((size_t)bh * NCHKS * DS + n) * DH + dbase;

    float4 v = *(const float4*)(g_hc + hb0);
    for (int c = 0; c < NCHKS; c++) {
        float decay = __expf(g_S[(size_t)bh * TT + c * CHK + CHK - 1]);
        size_t hb = hb0 + (size_t)c * cstride;
        __nv_bfloat162 p0, p1;
        p0.x = __float2bfloat16(hst.x); p0.y = __float2bfloat16(hst.y);
        p1.x = __float2bfloat16(hst.z); p1.y = __float2bfloat16(hst.w);
        *(__nv_bfloat162*)(g_hin + hb) = p0;
        *(__nv_bfloat162*)(g_hin + hb + 2) = p1;

        float4 vn = make_float4(0.f, 0.f, 0.f, 0.f);
        if (c + 1 < NCHKS) vn = *(const float4*)(g_hc + hb + cstride);
        hst.x = decay * hst.x + v.x;
        hst.y = decay * hst.y + v.y;
        hst.z = decay * hst.z + v.z;
        hst.w = decay * hst.w + v.w;
        v = vn;
    }
}

// ---------------- SSD phase C: inter-chunk Y + combine + gate ---------------
#define CO_C 0
#define CO_H 9216
#define CO_S 43008
#define C_SMEM 43264

__global__ void __launch_bounds__(256)
chunk_inter_k()
{
    extern __shared__ char sm[];
    uint32_t base = smem_u32(sm);
    float* S = (float*)(sm + CO_S);

    int tid = threadIdx.x;
    int wid = tid >> 5, lane = tid & 31;
    int wm = wid >> 2, wn = wid & 3;
    int chunk = blockIdx.x, h = blockIdx.y, b = blockIdx.z;
    int bh = b * NH + h;
    size_t rowbase = (size_t)b * TT + (size_t)chunk * CHK;

    const __nv_bfloat16* csrc = g_bcdt + rowbase * NCATP + 512 + h * 64;
    for (int i = tid; i < 512; i += 256) {
        int r = i >> 3, c = i & 7;
        CP_ASYNC16(base + CO_C + r * 144 + c * 16, csrc + (size_t)r * NCATP + c * 8);
    }
    const __nv_bfloat16* hsrc = g_hin + ((size_t)bh * NCHKS + chunk) * DS * DH;
    for (int i = tid; i < 2048; i += 256) {
        int r = i >> 5, c = i & 31;
        CP_ASYNC16(base + CO_H + r * 528 + c * 16, hsrc + (size_t)r * DH + c * 8);
    }
    if (tid < 64)
        CP_ASYNC4(base + CO_S + tid * 4, g_S + (size_t)bh * TT + chunk * CHK + tid);
    CP_COMMIT();
    CP_WAIT0();
    __syncthreads();

    float acc[2][8][4];
    #pragma unroll
    for (int i = 0; i < 2; i++)
        #pragma unroll
        for (int j = 0; j < 8; j++)
            #pragma unroll
            for (int f = 0; f < 4; f++) acc[i][j][f] = 0.f;

    #pragma unroll
    for (int ks = 0; ks < 4; ks++) {
        uint32_t a[2][4];
        #pragma unroll
        for (int i = 0; i < 2; i++) {
            int row = wm * 32 + i * 16 + (lane & 15);
            LDM_X4(a[i][0], a[i][1], a[i][2], a[i][3],
                   base + CO_C + (uint32_t)(row * 144 + ks * 32 + (lane >> 4) * 16));
        }
        #pragma unroll
        for (int jj = 0; jj < 4; jj++) {
            int n0 = wn * 64 + jj * 16;
            int grp = lane >> 3, l8 = lane & 7;
            uint32_t addr = base + CO_H
                + (uint32_t)(ks * 16 + (grp & 1) * 8 + l8) * 528
                + (uint32_t)(n0 + (grp >> 1) * 8) * 2;
            uint32_t b0, b1, b2, b3;
            LDM_X4T(b0, b1, b2, b3, addr);
            #pragma unroll
            for (int i = 0; i < 2; i++) {
                MMA16816(acc[i][jj * 2],     a[i][0], a[i][1], a[i][2], a[i][3], b0, b1);
                MMA16816(acc[i][jj * 2 + 1], a[i][0], a[i][1], a[i][2], a[i][3], b2, b3);
            }
        }
    }

    int gid = lane >> 2, t4 = lane & 3;
    #pragma unroll
    for (int i = 0; i < 2; i++)
        #pragma unroll
        for (int j8 = 0; j8 < 8; j8++)
            #pragma unroll
            for (int hf = 0; hf < 2; hf++) {
                int t = wm * 32 + i * 16 + gid + hf * 8;
                int d = wn * 64 + j8 * 8 + t4 * 2;
                float et = __expf(S[t]);
                size_t gi = (rowbase + t) * DI + h * DH + d;
                __nv_bfloat162 yi = *(const __nv_bfloat162*)(g_yi + gi);
                __nv_bfloat162 z2 = *(const __nv_bfloat162*)(g_xz + (rowbase + t) * (2 * DI) + DI + h * DH + d);
                float z0 = __bfloat162float(z2.x), z1 = __bfloat162float(z2.y);
                float y0 = acc[i][j8][hf * 2 + 0] * et + __bfloat162float(yi.x);
                float y1 = acc[i][j8][hf * 2 + 1] * et + __bfloat162float(yi.y);
                float s0 = z0 / (1.f + __expf(-z0));
                float s1 = z1 / (1.f + __expf(-z1));
                __nv_bfloat162 o;
                o.x = __float2bfloat16(y0 * s0);
                o.y = __float2bfloat16(y1 * s1);
                *(__nv_bfloat162*)(g_y + gi) = o;
            }
}

// ---------------- launch ----------------------------------------------------
extern "C" void kernel_launch(void* const* d_in, const int* in_sizes, int n_in,
                              void* d_out, int out_size)
{
    const float* x      = (const float*)d_in[0];
    const float* norm_w = (const float*)d_in[1];
    const float* in_w   = (const float*)d_in[2];
    const float* conv_w = (const float*)d_in[3];
    const float* conv_b = (const float*)d_in[4];
    const float* A_log  = (const float*)d_in[5];
    const float* B_w    = (const float*)d_in[6];
    const float* C_w    = (const float*)d_in[7];
    const float* dt_w   = (const float*)d_in[8];
    const float* dt_b   = (const float*)d_in[9];
    const float* Dp     = (const float*)d_in[10];
    const float* out_w  = (const float*)d_in[11];
    float* out = (float*)d_out;

    __nv_bfloat16 *p_xn, *p_xs, *p_y, *p_inw, *p_wcat, *p_outw, *p_bcdt, *p_xz;
    cudaGetSymbolAddress((void**)&p_xn, g_xn);
    cudaGetSymbolAddress((void**)&p_xz, g_xz);
    cudaGetSymbolAddress((void**)&p_xs, g_xs);
    cudaGetSymbolAddress((void**)&p_bcdt, g_bcdt);
    cudaGetSymbolAddress((void**)&p_y, g_y);
    cudaGetSymbolAddress((void**)&p_inw, g_inw);
    cudaGetSymbolAddress((void**)&p_wcat, g_wcat);
    cudaGetSymbolAddress((void**)&p_outw, g_outw);

    cudaFuncSetAttribute(gemm_mma<false, true>,  cudaFuncAttributeMaxDynamicSharedMemorySize, GEMM_SMEM);
    cudaFuncSetAttribute(gemm_mma<true, false>,  cudaFuncAttributeMaxDynamicSharedMemorySize, GEMM_SMEM);
    cudaFuncSetAttribute(chunk_intra_k, cudaFuncAttributeMaxDynamicSharedMemorySize, A_SMEM);
    cudaFuncSetAttribute(chunk_inter_k, cudaFuncAttributeMaxDynamicSharedMemorySize, C_SMEM);

    // fork a side stream for prep_rest (out_w + wcat), joined before gemm2
    cudaStream_t s2;
    cudaStreamCreate(&s2);
    cudaEvent_t e1, e2;
    cudaEventCreateWithFlags(&e1, cudaEventDisableTiming);
    cudaEventCreateWithFlags(&e2, cudaEventDisableTiming);

    // [main] in_w -> bf16 (gemm1 dependency)
    prep_inw_k<<<1024, 256>>>(in_w);
    cudaEventRecord(e1, 0);
    cudaStreamWaitEvent(s2, e1, 0);
    // [side] out_w + wcat -> bf16, overlapped with rmsnorm/gemm1/conv
    prep_rest_k<<<1024, 256, 0, s2>>>(out_w, B_w, C_w, dt_w);
    cudaEventRecord(e2, s2);

    // [main] RMSNorm -> bf16
    rmsnorm_k<<<NROWS / 8, 256>>>(x, norm_w);
    // [main] xz = xn @ in_w^T -> bf16
    gemm_mma<false, true><<<dim3(4096 / BN, NROWS / BM), 256, GEMM_SMEM>>>(
        p_xn, p_inw, (void*)p_xz, nullptr, NROWS, 2 * DI, DM);
    // [main] causal conv + SiLU -> bf16 (2 ch x 8 t per thread)
    conv_silu_k<<<dim3(DI / 512, TT / 8, BSZ), 256>>>(conv_w, conv_b);

    // join: wcat must be ready before gemm2
    cudaStreamWaitEvent(0, e2, 0);
    // [main] [B | C | dt] = xs @ wcat^T -> bf16
    gemm_mma<false, true><<<dim3(NCATP / BN, NROWS / BM), 256, GEMM_SMEM>>>(
        p_xs, p_wcat, (void*)p_bcdt, nullptr, NROWS, NCATP, DI);
    // [main] SSD phase A (+ D*x fused)
    chunk_intra_k<<<dim3(NCHKS, NH, BSZ), 256, A_SMEM>>>(A_log, dt_b, Dp);
    // [main] SSD phase B
    state_scan_k<<<dim3(16, NH, BSZ), 256>>>();
    // [main] SSD phase C
    chunk_inter_k<<<dim3(NCHKS, NH, BSZ), 256, C_SMEM>>>();
    // [main] out = y @ out_w^T + residual
    gemm_mma<true, false><<<dim3(1024 / BN, NROWS / BM), 256, GEMM_SMEM>>>(
        p_y, p_outw, (void*)out, x, NROWS, DM, DI);

    cudaEventDestroy(e1);
    cudaEventDestroy(e2);
    cudaStreamDestroy(s2);
}